// round 3
// baseline (speedup 1.0000x reference)
#include <cuda_runtime.h>
#include <math.h>

// Problem constants
#define Nn   100000
#define Ee   1600000
#define IND  128
#define Hh   64
#define Rr   4
#define Gg   128
#define OUTD 10
#define PCOLS 960   // 64 (W_skip) + 128 (F_skip) + 4 * (64 + 128)

// ---------------- scratch (static __device__ globals: allowed) --------------
// g_P as float4 array guarantees 16B alignment for vector gathers / red.v4.
__device__ float4 g_P4 [(size_t)Nn * PCOLS / 4];   // fused projections per layer
__device__ float  g_h  [(size_t)Nn * Hh];          // current node features
__device__ float4 g_acc4[(size_t)Nn * Hh / 4];     // skip + aggregated messages
__device__ int    g_cnt [Rr * Nn];
__device__ float  g_inv [Rr * Nn];
__device__ float  g_Wcat[64 * PCOLS];
__device__ float  g_pool[Gg * Hh];
__device__ float  g_t   [Gg * Hh];

// ---------------- small utility kernels ----------------
__global__ void zero_i(int* p, int n) {
    int i = blockIdx.x * blockDim.x + threadIdx.x;
    if (i < n) p[i] = 0;
}
__global__ void zero_f(float* p, int n) {
    int i = blockIdx.x * blockDim.x + threadIdx.x;
    if (i < n) p[i] = 0.f;
}

__global__ void count_edges(const int* __restrict__ ei, const int* __restrict__ et,
                            int* __restrict__ cnt) {
    int e = blockIdx.x * blockDim.x + threadIdx.x;
    if (e < Ee) {
        int d = __ldg(&ei[Ee + e]);
        int r = __ldg(&et[e]);
        atomicAdd(&cnt[r * Nn + d], 1);
    }
}

__global__ void inv_counts(const int* __restrict__ cnt, float* __restrict__ inv) {
    int i = blockIdx.x * blockDim.x + threadIdx.x;
    if (i < Rr * Nn) {
        int c = cnt[i];
        inv[i] = 1.0f / (float)(c > 0 ? c : 1);
    }
}

// Pack layer weights into Wcat [64 rows (i)] x [960 cols]
__global__ void repack(const float* __restrict__ Wskip, const float* __restrict__ Fskip,
                       const float* __restrict__ Wrel,  const float* __restrict__ Frel,
                       float* __restrict__ Wcat) {
    int idx = blockIdx.x * blockDim.x + threadIdx.x;
    if (idx >= 64 * PCOLS) return;
    int i = idx / PCOLS;
    int c = idx % PCOLS;
    float v;
    if (c < 64) {
        v = Wskip[i * 64 + c];
    } else if (c < 192) {
        v = Fskip[i * 128 + (c - 64)];
    } else {
        int cc = c - 192;
        int r = cc / 192;
        int o = cc % 192;
        if (o < 64) v = Wrel[((size_t)(r * 64 + i)) * 64 + o];
        else        v = Frel[((size_t)(r * 64 + i)) * 128 + (o - 64)];
    }
    Wcat[i * PCOLS + c] = v;
}

// ---------------- tiled SGEMM: C[N,M] = A[N,K] @ B[K,M] (+bias) ----------------
// 64x64 block tile, 4x4 per-thread microtile, K in chunks of 64.
__global__ __launch_bounds__(256)
void sgemm(const float* __restrict__ A, const float* __restrict__ B,
           float* __restrict__ C, int N, int K, int M,
           const float* __restrict__ bias) {
    __shared__ float As[64][64];
    __shared__ float Bs[64][64];
    int tid = threadIdx.x;
    int tx = tid & 15, ty = tid >> 4;
    int n0 = blockIdx.y * 64, m0 = blockIdx.x * 64;

    float c[4][4];
    #pragma unroll
    for (int i = 0; i < 4; i++)
        #pragma unroll
        for (int j = 0; j < 4; j++) c[i][j] = 0.f;

    for (int kb = 0; kb < K; kb += 64) {
        #pragma unroll
        for (int i = 0; i < 16; i++) {
            int idx = tid + i * 256;
            int r = idx >> 6, k = idx & 63;
            int n = n0 + r;
            As[r][k] = (n < N) ? A[(size_t)n * K + kb + k] : 0.f;
        }
        #pragma unroll
        for (int i = 0; i < 16; i++) {
            int idx = tid + i * 256;
            int r = idx >> 6, m = idx & 63;
            Bs[r][m] = B[(size_t)(kb + r) * M + m0 + m];
        }
        __syncthreads();
        #pragma unroll 16
        for (int k = 0; k < 64; k++) {
            float4 bv = *reinterpret_cast<const float4*>(&Bs[k][tx * 4]);
            float a0 = As[ty * 4 + 0][k];
            float a1 = As[ty * 4 + 1][k];
            float a2 = As[ty * 4 + 2][k];
            float a3 = As[ty * 4 + 3][k];
            c[0][0] += a0 * bv.x; c[0][1] += a0 * bv.y; c[0][2] += a0 * bv.z; c[0][3] += a0 * bv.w;
            c[1][0] += a1 * bv.x; c[1][1] += a1 * bv.y; c[1][2] += a1 * bv.z; c[1][3] += a1 * bv.w;
            c[2][0] += a2 * bv.x; c[2][1] += a2 * bv.y; c[2][2] += a2 * bv.z; c[2][3] += a2 * bv.w;
            c[3][0] += a3 * bv.x; c[3][1] += a3 * bv.y; c[3][2] += a3 * bv.z; c[3][3] += a3 * bv.w;
        }
        __syncthreads();
    }

    #pragma unroll
    for (int i = 0; i < 4; i++) {
        int n = n0 + ty * 4 + i;
        if (n < N) {
            #pragma unroll
            for (int j = 0; j < 4; j++) {
                int m = m0 + tx * 4 + j;
                float v = c[i][j];
                if (bias) v += bias[m];
                C[(size_t)n * M + m] = v;
            }
        }
    }
}

// ---------------- skip path: acc = relu(gamma_s * hW + beta_s) ----------------
__global__ void skip_init(const float* __restrict__ P, float* __restrict__ acc) {
    int idx = blockIdx.x * blockDim.x + threadIdx.x;
    if (idx >= Nn * Hh) return;
    int n = idx >> 6, o = idx & 63;
    const float* row = P + (size_t)n * PCOLS;
    float hw = __ldg(&row[o]);
    float be = __ldg(&row[64 + o]);
    float ga = __ldg(&row[128 + o]);
    acc[idx] = fmaxf(ga * hw + be, 0.f);
}

// ---------------- edge messages: 16 threads per edge ----------------
// Lane 0 of each 16-thread group loads indices + inv; broadcast via shfl.
__global__ __launch_bounds__(256)
void edge_msgs(const int* __restrict__ ei, const int* __restrict__ et,
               const float* __restrict__ P, const float* __restrict__ inv,
               float* __restrict__ acc) {
    int lane = threadIdx.x & 31;
    int grp  = lane >> 4;                 // 0 or 1 within warp
    int t    = lane & 15;                 // position within group
    int e = blockIdx.x * 16 + (threadIdx.x >> 4);
    if (e >= Ee) return;

    int s = 0, d = 0, r = 0;
    float ic = 0.f;
    if (t == 0) {
        s  = __ldg(&ei[e]);
        d  = __ldg(&ei[Ee + e]);
        r  = __ldg(&et[e]);
        ic = __ldg(&inv[r * Nn + d]);
    }
    int srcLane = grp << 4;
    s  = __shfl_sync(0xFFFFFFFFu, s,  srcLane);
    d  = __shfl_sync(0xFFFFFFFFu, d,  srcLane);
    r  = __shfl_sync(0xFFFFFFFFu, r,  srcLane);
    ic = __shfl_sync(0xFFFFFFFFu, ic, srcLane);

    size_t relOff = 192 + (size_t)r * 192;
    const float4* hp = reinterpret_cast<const float4*>(P + (size_t)s * PCOLS + relOff);
    const float4* bp = reinterpret_cast<const float4*>(P + (size_t)d * PCOLS + relOff + 64);
    const float4* gp = reinterpret_cast<const float4*>(P + (size_t)d * PCOLS + relOff + 128);
    float4 h = __ldg(&hp[t]);
    float4 b = __ldg(&bp[t]);
    float4 g = __ldg(&gp[t]);
    float4 m;
    m.x = fmaxf(g.x * h.x + b.x, 0.f) * ic;
    m.y = fmaxf(g.y * h.y + b.y, 0.f) * ic;
    m.z = fmaxf(g.z * h.z + b.z, 0.f) * ic;
    m.w = fmaxf(g.w * h.w + b.w, 0.f) * ic;
    float* out = acc + (size_t)d * Hh + t * 4;
    asm volatile("red.global.add.v4.f32 [%0], {%1, %2, %3, %4};"
                 :: "l"(out), "f"(m.x), "f"(m.y), "f"(m.z), "f"(m.w) : "memory");
}

// ---------------- BN (eval) + ReLU ----------------
__global__ void bn_relu(const float* __restrict__ acc, const float* __restrict__ bg,
                        const float* __restrict__ bb, float* __restrict__ out) {
    int idx = blockIdx.x * blockDim.x + threadIdx.x;
    if (idx >= Nn * Hh) return;
    int o = idx & 63;
    float s = __ldg(&bg[o]) * rsqrtf(1.0f + 1e-5f);
    out[idx] = fmaxf(acc[idx] * s + __ldg(&bb[o]), 0.f);
}

// ---------------- global add pool ----------------
__global__ void pool_add(const float* __restrict__ h, const int* __restrict__ batch,
                         float* __restrict__ pool) {
    int idx = blockIdx.x * blockDim.x + threadIdx.x;
    if (idx >= Nn * Hh) return;
    int n = idx >> 6, o = idx & 63;
    atomicAdd(&pool[__ldg(&batch[n]) * Hh + o], h[idx]);
}

// ---------------- head ----------------
__global__ void head1(const float* __restrict__ pool, const float* __restrict__ W,
                      const float* __restrict__ b, float* __restrict__ t) {
    int idx = blockIdx.x * blockDim.x + threadIdx.x;
    if (idx >= Gg * Hh) return;
    int r = idx >> 6, o = idx & 63;
    float s = 0.f;
    #pragma unroll 8
    for (int k = 0; k < Hh; k++) s += pool[r * Hh + k] * W[k * Hh + o];
    t[idx] = fmaxf(s + b[o], 0.f);
}
__global__ void head2(const float* __restrict__ t, const float* __restrict__ W,
                      const float* __restrict__ b, float* __restrict__ out) {
    int idx = blockIdx.x * blockDim.x + threadIdx.x;
    if (idx >= Gg * OUTD) return;
    int r = idx / OUTD, o = idx % OUTD;
    float s = 0.f;
    #pragma unroll 8
    for (int k = 0; k < Hh; k++) s += t[r * Hh + k] * W[k * OUTD + o];
    out[idx] = s + b[o];
}

// ---------------- launch ----------------
extern "C" void kernel_launch(void* const* d_in, const int* in_sizes, int n_in,
                              void* d_out, int out_size) {
    const float* x      = (const float*)d_in[0];
    const int*   ei     = (const int*)  d_in[1];
    const int*   etype  = (const int*)  d_in[2];
    const int*   batch  = (const int*)  d_in[3];
    const float* enc_W  = (const float*)d_in[4];
    const float* enc_b  = (const float*)d_in[5];
    const float* Wskip0 = (const float*)d_in[6];
    const float* Fskip0 = (const float*)d_in[7];
    const float* Wrel0  = (const float*)d_in[8];
    const float* Frel0  = (const float*)d_in[9];
    const float* Wskip1 = (const float*)d_in[10];
    const float* Fskip1 = (const float*)d_in[11];
    const float* Wrel1  = (const float*)d_in[12];
    const float* Frel1  = (const float*)d_in[13];
    const float* bn_g   = (const float*)d_in[14];
    const float* bn_b   = (const float*)d_in[15];
    const float* lin_W  = (const float*)d_in[16];
    const float* lin_b  = (const float*)d_in[17];
    const float* clf_W  = (const float*)d_in[18];
    const float* clf_b  = (const float*)d_in[19];
    float* out = (float*)d_out;

    float *pH, *pP, *pAcc, *pInv, *pWcat, *pPool, *pT;
    int* pCnt;
    cudaGetSymbolAddress((void**)&pH,    g_h);
    cudaGetSymbolAddress((void**)&pP,    g_P4);
    cudaGetSymbolAddress((void**)&pAcc,  g_acc4);
    cudaGetSymbolAddress((void**)&pCnt,  g_cnt);
    cudaGetSymbolAddress((void**)&pInv,  g_inv);
    cudaGetSymbolAddress((void**)&pWcat, g_Wcat);
    cudaGetSymbolAddress((void**)&pPool, g_pool);
    cudaGetSymbolAddress((void**)&pT,    g_t);

    const int NT = 256;
    int nNodeElems = Nn * Hh;

    // Edge counts (identical for both layers)
    zero_i<<<(Rr * Nn + NT - 1) / NT, NT>>>(pCnt, Rr * Nn);
    count_edges<<<(Ee + 511) / 512, 512>>>(ei, etype, pCnt);
    inv_counts<<<(Rr * Nn + NT - 1) / NT, NT>>>(pCnt, pInv);

    // Encoder: h = x @ enc_W + enc_b
    {
        dim3 grid(1, (Nn + 63) / 64);
        sgemm<<<grid, 256>>>(x, enc_W, pH, Nn, IND, Hh, enc_b);
    }

    // ---- FiLMConv layer 0 ----
    repack<<<(64 * PCOLS + NT - 1) / NT, NT>>>(Wskip0, Fskip0, Wrel0, Frel0, pWcat);
    {
        dim3 grid(PCOLS / 64, (Nn + 63) / 64);
        sgemm<<<grid, 256>>>(pH, pWcat, pP, Nn, Hh, PCOLS, nullptr);
    }
    skip_init<<<(nNodeElems + NT - 1) / NT, NT>>>(pP, pAcc);
    edge_msgs<<<(Ee + 15) / 16, 256>>>(ei, etype, pP, pInv, pAcc);

    // BN + ReLU -> h
    bn_relu<<<(nNodeElems + NT - 1) / NT, NT>>>(pAcc, bn_g, bn_b, pH);

    // ---- FiLMConv layer 1 ----
    repack<<<(64 * PCOLS + NT - 1) / NT, NT>>>(Wskip1, Fskip1, Wrel1, Frel1, pWcat);
    {
        dim3 grid(PCOLS / 64, (Nn + 63) / 64);
        sgemm<<<grid, 256>>>(pH, pWcat, pP, Nn, Hh, PCOLS, nullptr);
    }
    skip_init<<<(nNodeElems + NT - 1) / NT, NT>>>(pP, pAcc);
    edge_msgs<<<(Ee + 15) / 16, 256>>>(ei, etype, pP, pInv, pAcc);

    // ---- pooling + head ----
    zero_f<<<(Gg * Hh + NT - 1) / NT, NT>>>(pPool, Gg * Hh);
    pool_add<<<(nNodeElems + NT - 1) / NT, NT>>>(pAcc, batch, pPool);
    head1<<<(Gg * Hh + NT - 1) / NT, NT>>>(pPool, lin_W, lin_b, pT);
    head2<<<(Gg * OUTD + NT - 1) / NT, NT>>>(pT, clf_W, clf_b, out);
}

// round 5
// speedup vs baseline: 1.1455x; 1.1455x over previous
#include <cuda_runtime.h>
#include <math.h>

// Problem constants
#define Nn   100000
#define Ee   1600000
#define IND  128
#define Hh   64
#define Rr   4
#define Gg   128
#define OUTD 10
#define PCOLS 960   // 64 (W_skip) + 128 (F_skip) + 4 * (64 + 128)

// ---------------- scratch (static __device__ globals: allowed) --------------
__device__ float4 g_P4 [(size_t)Nn * PCOLS / 4];   // fused projections per layer
__device__ float  g_h  [(size_t)Nn * Hh];          // current node features
__device__ float4 g_acc4[(size_t)Nn * Hh / 4];     // skip + aggregated messages
__device__ int    g_cnt [Rr * Nn];
__device__ float  g_inv [Rr * Nn];
__device__ float  g_Wcat[64 * PCOLS];
__device__ float  g_pool[Gg * Hh];
__device__ float  g_t   [Gg * Hh];

// ---------------- small utility kernels ----------------
__global__ void zero_i(int* p, int n) {
    int i = blockIdx.x * blockDim.x + threadIdx.x;
    if (i < n) p[i] = 0;
}
__global__ void zero_f(float* p, int n) {
    int i = blockIdx.x * blockDim.x + threadIdx.x;
    if (i < n) p[i] = 0.f;
}

__global__ void count_edges(const int* __restrict__ ei, const int* __restrict__ et,
                            int* __restrict__ cnt) {
    int e = blockIdx.x * blockDim.x + threadIdx.x;
    if (e < Ee) {
        int d = __ldg(&ei[Ee + e]);
        int r = __ldg(&et[e]);
        atomicAdd(&cnt[r * Nn + d], 1);
    }
}

__global__ void inv_counts(const int* __restrict__ cnt, float* __restrict__ inv) {
    int i = blockIdx.x * blockDim.x + threadIdx.x;
    if (i < Rr * Nn) {
        int c = cnt[i];
        inv[i] = 1.0f / (float)(c > 0 ? c : 1);
    }
}

// Pack layer weights into Wcat [64 rows (i)] x [960 cols]
__global__ void repack(const float* __restrict__ Wskip, const float* __restrict__ Fskip,
                       const float* __restrict__ Wrel,  const float* __restrict__ Frel,
                       float* __restrict__ Wcat) {
    int idx = blockIdx.x * blockDim.x + threadIdx.x;
    if (idx >= 64 * PCOLS) return;
    int i = idx / PCOLS;
    int c = idx % PCOLS;
    float v;
    if (c < 64) {
        v = Wskip[i * 64 + c];
    } else if (c < 192) {
        v = Fskip[i * 128 + (c - 64)];
    } else {
        int cc = c - 192;
        int r = cc / 192;
        int o = cc % 192;
        if (o < 64) v = Wrel[((size_t)(r * 64 + i)) * 64 + o];
        else        v = Frel[((size_t)(r * 64 + i)) * 128 + (o - 64)];
    }
    Wcat[i * PCOLS + c] = v;
}

// ---------------- generic tiled SGEMM (encoder only) ----------------
__global__ __launch_bounds__(256)
void sgemm(const float* __restrict__ A, const float* __restrict__ B,
           float* __restrict__ C, int N, int K, int M,
           const float* __restrict__ bias) {
    __shared__ float As[64][64];
    __shared__ float Bs[64][64];
    int tid = threadIdx.x;
    int tx = tid & 15, ty = tid >> 4;
    int n0 = blockIdx.y * 64, m0 = blockIdx.x * 64;

    float c[4][4];
    #pragma unroll
    for (int i = 0; i < 4; i++)
        #pragma unroll
        for (int j = 0; j < 4; j++) c[i][j] = 0.f;

    for (int kb = 0; kb < K; kb += 64) {
        #pragma unroll
        for (int i = 0; i < 16; i++) {
            int idx = tid + i * 256;
            int r = idx >> 6, k = idx & 63;
            int n = n0 + r;
            As[r][k] = (n < N) ? A[(size_t)n * K + kb + k] : 0.f;
        }
        #pragma unroll
        for (int i = 0; i < 16; i++) {
            int idx = tid + i * 256;
            int r = idx >> 6, m = idx & 63;
            Bs[r][m] = B[(size_t)(kb + r) * M + m0 + m];
        }
        __syncthreads();
        #pragma unroll 16
        for (int k = 0; k < 64; k++) {
            float4 bv = *reinterpret_cast<const float4*>(&Bs[k][tx * 4]);
            float a0 = As[ty * 4 + 0][k];
            float a1 = As[ty * 4 + 1][k];
            float a2 = As[ty * 4 + 2][k];
            float a3 = As[ty * 4 + 3][k];
            c[0][0] += a0 * bv.x; c[0][1] += a0 * bv.y; c[0][2] += a0 * bv.z; c[0][3] += a0 * bv.w;
            c[1][0] += a1 * bv.x; c[1][1] += a1 * bv.y; c[1][2] += a1 * bv.z; c[1][3] += a1 * bv.w;
            c[2][0] += a2 * bv.x; c[2][1] += a2 * bv.y; c[2][2] += a2 * bv.z; c[2][3] += a2 * bv.w;
            c[3][0] += a3 * bv.x; c[3][1] += a3 * bv.y; c[3][2] += a3 * bv.z; c[3][3] += a3 * bv.w;
        }
        __syncthreads();
    }

    #pragma unroll
    for (int i = 0; i < 4; i++) {
        int n = n0 + ty * 4 + i;
        if (n < N) {
            #pragma unroll
            for (int j = 0; j < 4; j++) {
                int m = m0 + tx * 4 + j;
                float v = c[i][j];
                if (bias) v += bias[m];
                C[(size_t)n * M + m] = v;
            }
        }
    }
}

// ---------------- fused layer GEMM: P[N,960] = A[N,64] @ B[64,960] ----------------
// 128-row block, A-tile resident in smem (k-major), 15 column chunks of 64,
// 8x4 microtile per thread (32 FFMA per 3 LDS.128).
__global__ __launch_bounds__(256)
void film_gemm(const float* __restrict__ A, const float* __restrict__ B,
               float* __restrict__ P, int N) {
    __shared__ float As[64 * 128];   // [k][row]
    __shared__ float Bs[64 * 64];    // [k][col]
    int tid = threadIdx.x;
    int tx = tid & 15;        // column group: 4 cols
    int ty = tid >> 4;        // row group: 8 rows
    int n0 = blockIdx.x * 128;

    // Load A tile (128 rows x 64 k), store transposed k-major.
    #pragma unroll
    for (int it = 0; it < 8; it++) {
        int idx = (it * 256 + tid) * 4;      // element index within tile
        int row = idx >> 6;
        int k   = idx & 63;
        int n = n0 + row;
        float4 v = (n < N) ? *reinterpret_cast<const float4*>(&A[(size_t)n * 64 + k])
                           : make_float4(0.f, 0.f, 0.f, 0.f);
        As[(k + 0) * 128 + row] = v.x;
        As[(k + 1) * 128 + row] = v.y;
        As[(k + 2) * 128 + row] = v.z;
        As[(k + 3) * 128 + row] = v.w;
    }

    for (int c = 0; c < 15; c++) {
        __syncthreads();  // previous chunk's compute done before overwriting Bs
        #pragma unroll
        for (int it = 0; it < 4; it++) {
            int idx = it * 256 + tid;        // float4 index in 64x64 chunk
            int k   = idx >> 4;
            int col = (idx & 15) * 4;
            *reinterpret_cast<float4*>(&Bs[k * 64 + col]) =
                *reinterpret_cast<const float4*>(&B[(size_t)k * PCOLS + c * 64 + col]);
        }
        __syncthreads();

        float4 acc0 = make_float4(0.f,0.f,0.f,0.f), acc1 = acc0, acc2 = acc0, acc3 = acc0;
        float4 acc4 = acc0, acc5 = acc0, acc6 = acc0, acc7 = acc0;

        #pragma unroll 8
        for (int k = 0; k < 64; k++) {
            float4 b  = *reinterpret_cast<const float4*>(&Bs[k * 64 + tx * 4]);
            float4 a0 = *reinterpret_cast<const float4*>(&As[k * 128 + ty * 8]);
            float4 a1 = *reinterpret_cast<const float4*>(&As[k * 128 + ty * 8 + 4]);
            acc0.x += a0.x * b.x; acc0.y += a0.x * b.y; acc0.z += a0.x * b.z; acc0.w += a0.x * b.w;
            acc1.x += a0.y * b.x; acc1.y += a0.y * b.y; acc1.z += a0.y * b.z; acc1.w += a0.y * b.w;
            acc2.x += a0.z * b.x; acc2.y += a0.z * b.y; acc2.z += a0.z * b.z; acc2.w += a0.z * b.w;
            acc3.x += a0.w * b.x; acc3.y += a0.w * b.y; acc3.z += a0.w * b.z; acc3.w += a0.w * b.w;
            acc4.x += a1.x * b.x; acc4.y += a1.x * b.y; acc4.z += a1.x * b.z; acc4.w += a1.x * b.w;
            acc5.x += a1.y * b.x; acc5.y += a1.y * b.y; acc5.z += a1.y * b.z; acc5.w += a1.y * b.w;
            acc6.x += a1.z * b.x; acc6.y += a1.z * b.y; acc6.z += a1.z * b.z; acc6.w += a1.z * b.w;
            acc7.x += a1.w * b.x; acc7.y += a1.w * b.y; acc7.z += a1.w * b.z; acc7.w += a1.w * b.w;
        }

        int colBase = c * 64 + tx * 4;
        int nb = n0 + ty * 8;
        float4* accs[8] = {&acc0,&acc1,&acc2,&acc3,&acc4,&acc5,&acc6,&acc7};
        #pragma unroll
        for (int i = 0; i < 8; i++) {
            int n = nb + i;
            if (n < N)
                *reinterpret_cast<float4*>(&P[(size_t)n * PCOLS + colBase]) = *accs[i];
        }
    }
}

// ---------------- skip path: acc = relu(gamma_s * hW + beta_s) ----------------
__global__ void skip_init(const float* __restrict__ P, float* __restrict__ acc) {
    int idx = blockIdx.x * blockDim.x + threadIdx.x;
    if (idx >= Nn * Hh) return;
    int n = idx >> 6, o = idx & 63;
    const float* row = P + (size_t)n * PCOLS;
    float hw = __ldg(&row[o]);
    float be = __ldg(&row[64 + o]);
    float ga = __ldg(&row[128 + o]);
    acc[idx] = fmaxf(ga * hw + be, 0.f);
}

// ---------------- edge messages: 16 threads per edge ----------------
// NOTE: Ee/16 divides exactly -> every launched thread is active (shfl-safe).
__global__ __launch_bounds__(256)
void edge_msgs(const int* __restrict__ ei, const int* __restrict__ et,
               const float* __restrict__ P, const float* __restrict__ inv,
               float* __restrict__ acc) {
    int lane = threadIdx.x & 31;
    int grp  = lane >> 4;
    int t    = lane & 15;
    int e = blockIdx.x * 16 + (threadIdx.x >> 4);
    if (e >= Ee) return;

    int s = 0, d = 0, r = 0;
    float ic = 0.f;
    if (t == 0) {
        s  = __ldg(&ei[e]);
        d  = __ldg(&ei[Ee + e]);
        r  = __ldg(&et[e]);
        ic = __ldg(&inv[r * Nn + d]);
    }
    int srcLane = grp << 4;
    s  = __shfl_sync(0xFFFFFFFFu, s,  srcLane);
    d  = __shfl_sync(0xFFFFFFFFu, d,  srcLane);
    r  = __shfl_sync(0xFFFFFFFFu, r,  srcLane);
    ic = __shfl_sync(0xFFFFFFFFu, ic, srcLane);

    size_t relOff = 192 + (size_t)r * 192;
    const float4* hp = reinterpret_cast<const float4*>(P + (size_t)s * PCOLS + relOff);
    const float4* bp = reinterpret_cast<const float4*>(P + (size_t)d * PCOLS + relOff + 64);
    const float4* gp = reinterpret_cast<const float4*>(P + (size_t)d * PCOLS + relOff + 128);
    float4 h = __ldg(&hp[t]);
    float4 b = __ldg(&bp[t]);
    float4 g = __ldg(&gp[t]);
    float4 m;
    m.x = fmaxf(g.x * h.x + b.x, 0.f) * ic;
    m.y = fmaxf(g.y * h.y + b.y, 0.f) * ic;
    m.z = fmaxf(g.z * h.z + b.z, 0.f) * ic;
    m.w = fmaxf(g.w * h.w + b.w, 0.f) * ic;
    float* out = acc + (size_t)d * Hh + t * 4;
    asm volatile("red.global.add.v4.f32 [%0], {%1, %2, %3, %4};"
                 :: "l"(out), "f"(m.x), "f"(m.y), "f"(m.z), "f"(m.w) : "memory");
}

// ---------------- BN (eval) + ReLU ----------------
__global__ void bn_relu(const float* __restrict__ acc, const float* __restrict__ bg,
                        const float* __restrict__ bb, float* __restrict__ out) {
    int idx = blockIdx.x * blockDim.x + threadIdx.x;
    if (idx >= Nn * Hh) return;
    int o = idx & 63;
    float s = __ldg(&bg[o]) * rsqrtf(1.0f + 1e-5f);
    out[idx] = fmaxf(acc[idx] * s + __ldg(&bb[o]), 0.f);
}

// ---------------- global add pool ----------------
__global__ void pool_add(const float* __restrict__ h, const int* __restrict__ batch,
                         float* __restrict__ pool) {
    int idx = blockIdx.x * blockDim.x + threadIdx.x;
    if (idx >= Nn * Hh) return;
    int n = idx >> 6, o = idx & 63;
    atomicAdd(&pool[__ldg(&batch[n]) * Hh + o], h[idx]);
}

// ---------------- head ----------------
__global__ void head1(const float* __restrict__ pool, const float* __restrict__ W,
                      const float* __restrict__ b, float* __restrict__ t) {
    int idx = blockIdx.x * blockDim.x + threadIdx.x;
    if (idx >= Gg * Hh) return;
    int r = idx >> 6, o = idx & 63;
    float s = 0.f;
    #pragma unroll 8
    for (int k = 0; k < Hh; k++) s += pool[r * Hh + k] * W[k * Hh + o];
    t[idx] = fmaxf(s + b[o], 0.f);
}
__global__ void head2(const float* __restrict__ t, const float* __restrict__ W,
                      const float* __restrict__ b, float* __restrict__ out) {
    int idx = blockIdx.x * blockDim.x + threadIdx.x;
    if (idx >= Gg * OUTD) return;
    int r = idx / OUTD, o = idx % OUTD;
    float s = 0.f;
    #pragma unroll 8
    for (int k = 0; k < Hh; k++) s += t[r * Hh + k] * W[k * OUTD + o];
    out[idx] = s + b[o];
}

// ---------------- launch ----------------
extern "C" void kernel_launch(void* const* d_in, const int* in_sizes, int n_in,
                              void* d_out, int out_size) {
    const float* x      = (const float*)d_in[0];
    const int*   ei     = (const int*)  d_in[1];
    const int*   etype  = (const int*)  d_in[2];
    const int*   batch  = (const int*)  d_in[3];
    const float* enc_W  = (const float*)d_in[4];
    const float* enc_b  = (const float*)d_in[5];
    const float* Wskip0 = (const float*)d_in[6];
    const float* Fskip0 = (const float*)d_in[7];
    const float* Wrel0  = (const float*)d_in[8];
    const float* Frel0  = (const float*)d_in[9];
    const float* Wskip1 = (const float*)d_in[10];
    const float* Fskip1 = (const float*)d_in[11];
    const float* Wrel1  = (const float*)d_in[12];
    const float* Frel1  = (const float*)d_in[13];
    const float* bn_g   = (const float*)d_in[14];
    const float* bn_b   = (const float*)d_in[15];
    const float* lin_W  = (const float*)d_in[16];
    const float* lin_b  = (const float*)d_in[17];
    const float* clf_W  = (const float*)d_in[18];
    const float* clf_b  = (const float*)d_in[19];
    float* out = (float*)d_out;

    float *pH, *pP, *pAcc, *pInv, *pWcat, *pPool, *pT;
    int* pCnt;
    cudaGetSymbolAddress((void**)&pH,    g_h);
    cudaGetSymbolAddress((void**)&pP,    g_P4);
    cudaGetSymbolAddress((void**)&pAcc,  g_acc4);
    cudaGetSymbolAddress((void**)&pCnt,  g_cnt);
    cudaGetSymbolAddress((void**)&pInv,  g_inv);
    cudaGetSymbolAddress((void**)&pWcat, g_Wcat);
    cudaGetSymbolAddress((void**)&pPool, g_pool);
    cudaGetSymbolAddress((void**)&pT,    g_t);

    const int NT = 256;
    int nNodeElems = Nn * Hh;
    int gemmBlocks = (Nn + 127) / 128;

    // Edge counts (identical for both layers)
    zero_i<<<(Rr * Nn + NT - 1) / NT, NT>>>(pCnt, Rr * Nn);
    count_edges<<<(Ee + 511) / 512, 512>>>(ei, etype, pCnt);
    inv_counts<<<(Rr * Nn + NT - 1) / NT, NT>>>(pCnt, pInv);

    // Encoder: h = x @ enc_W + enc_b
    {
        dim3 grid(1, (Nn + 63) / 64);
        sgemm<<<grid, 256>>>(x, enc_W, pH, Nn, IND, Hh, enc_b);
    }

    // ---- FiLMConv layer 0 ----
    repack<<<(64 * PCOLS + NT - 1) / NT, NT>>>(Wskip0, Fskip0, Wrel0, Frel0, pWcat);
    film_gemm<<<gemmBlocks, 256>>>(pH, pWcat, pP, Nn);
    skip_init<<<(nNodeElems + NT - 1) / NT, NT>>>(pP, pAcc);
    edge_msgs<<<Ee / 16, 256>>>(ei, etype, pP, pInv, pAcc);

    // BN + ReLU -> h
    bn_relu<<<(nNodeElems + NT - 1) / NT, NT>>>(pAcc, bn_g, bn_b, pH);

    // ---- FiLMConv layer 1 ----
    repack<<<(64 * PCOLS + NT - 1) / NT, NT>>>(Wskip1, Fskip1, Wrel1, Frel1, pWcat);
    film_gemm<<<gemmBlocks, 256>>>(pH, pWcat, pP, Nn);
    skip_init<<<(nNodeElems + NT - 1) / NT, NT>>>(pP, pAcc);
    edge_msgs<<<Ee / 16, 256>>>(ei, etype, pP, pInv, pAcc);

    // ---- pooling + head ----
    zero_f<<<(Gg * Hh + NT - 1) / NT, NT>>>(pPool, Gg * Hh);
    pool_add<<<(nNodeElems + NT - 1) / NT, NT>>>(pAcc, batch, pPool);
    head1<<<(Gg * Hh + NT - 1) / NT, NT>>>(pPool, lin_W, lin_b, pT);
    head2<<<(Gg * OUTD + NT - 1) / NT, NT>>>(pT, clf_W, clf_b, out);
}

// round 7
// speedup vs baseline: 1.3541x; 1.1821x over previous
#include <cuda_runtime.h>
#include <math.h>

// Problem constants
#define Nn   100000
#define Ee   1600000
#define IND  128
#define Hh   64
#define Rr   4
#define Gg   128
#define OUTD 10
#define PCOLS 960   // 64 (W_skip) + 128 (F_skip) + 4 * (64 + 128)
#define RN   (Rr * Nn)          // 400000 (r,dst) keys
#define SCAN_B 1024
#define NBLK ((RN + SCAN_B - 1) / SCAN_B)   // 391

// ---------------- scratch (static __device__ globals: allowed) --------------
__device__ float4 g_P4 [(size_t)Nn * PCOLS / 4];   // fused projections per layer
__device__ float  g_h  [(size_t)Nn * Hh];          // current node features
__device__ int    g_cnt [RN];
__device__ float  g_inv [RN];
__device__ int    g_off [RN + 1];
__device__ int    g_fill[RN];
__device__ int    g_bsum[512];
__device__ int    g_srcs[Ee];
__device__ float  g_Wcat[64 * PCOLS];
__device__ float  g_pool[Gg * Hh];
__device__ float  g_t   [Gg * Hh];

// ---------------- small utility kernels ----------------
__global__ void zero_i(int* p, int n) {
    int i = blockIdx.x * blockDim.x + threadIdx.x;
    if (i < n) p[i] = 0;
}
__global__ void zero_f(float* p, int n) {
    int i = blockIdx.x * blockDim.x + threadIdx.x;
    if (i < n) p[i] = 0.f;
}

// key = dst*4 + rel
__global__ void count_edges(const int* __restrict__ ei, const int* __restrict__ et,
                            int* __restrict__ cnt) {
    int e = blockIdx.x * blockDim.x + threadIdx.x;
    if (e < Ee) {
        int d = __ldg(&ei[Ee + e]);
        int r = __ldg(&et[e]);
        atomicAdd(&cnt[d * Rr + r], 1);
    }
}

__global__ void inv_counts(const int* __restrict__ cnt, float* __restrict__ inv) {
    int i = blockIdx.x * blockDim.x + threadIdx.x;
    if (i < RN) {
        int c = cnt[i];
        inv[i] = 1.0f / (float)(c > 0 ? c : 1);
    }
}

// ---------------- exclusive scan (3-kernel) over cnt -> off ----------------
__global__ void scan1(const int* __restrict__ cnt, int* __restrict__ off,
                      int* __restrict__ bsum) {
    __shared__ int sh[SCAN_B];
    int t = threadIdx.x;
    int i = blockIdx.x * SCAN_B + t;
    int v = (i < RN) ? cnt[i] : 0;
    sh[t] = v;
    __syncthreads();
    for (int d = 1; d < SCAN_B; d <<= 1) {
        int x = (t >= d) ? sh[t - d] : 0;
        __syncthreads();
        sh[t] += x;
        __syncthreads();
    }
    if (i < RN) off[i] = sh[t] - v;
    if (t == SCAN_B - 1) bsum[blockIdx.x] = sh[t];
}
__global__ void scan2(int* __restrict__ bsum, int n) {
    __shared__ int sh[512];
    int t = threadIdx.x;
    int v = (t < n) ? bsum[t] : 0;
    sh[t] = v;
    __syncthreads();
    for (int d = 1; d < 512; d <<= 1) {
        int x = (t >= d) ? sh[t - d] : 0;
        __syncthreads();
        sh[t] += x;
        __syncthreads();
    }
    if (t < n) bsum[t] = sh[t] - v;   // exclusive
}
__global__ void scan3(int* __restrict__ off, const int* __restrict__ bsum) {
    int i = blockIdx.x * blockDim.x + threadIdx.x;
    if (i < RN) off[i] += bsum[i / SCAN_B];
    if (i == 0) off[RN] = Ee;
}

// ---------------- scatter edges into CSR (src only) ----------------
__global__ void scatter_edges(const int* __restrict__ ei, const int* __restrict__ et,
                              const int* __restrict__ off, int* __restrict__ fill,
                              int* __restrict__ srcs) {
    int e = blockIdx.x * blockDim.x + threadIdx.x;
    if (e >= Ee) return;
    int d = __ldg(&ei[Ee + e]);
    int r = __ldg(&et[e]);
    int key = d * Rr + r;
    int pos = off[key] + atomicAdd(&fill[key], 1);
    srcs[pos] = __ldg(&ei[e]);
}

// Pack layer weights into Wcat [64 rows (i)] x [960 cols]
__global__ void repack(const float* __restrict__ Wskip, const float* __restrict__ Fskip,
                       const float* __restrict__ Wrel,  const float* __restrict__ Frel,
                       float* __restrict__ Wcat) {
    int idx = blockIdx.x * blockDim.x + threadIdx.x;
    if (idx >= 64 * PCOLS) return;
    int i = idx / PCOLS;
    int c = idx % PCOLS;
    float v;
    if (c < 64) {
        v = Wskip[i * 64 + c];
    } else if (c < 192) {
        v = Fskip[i * 128 + (c - 64)];
    } else {
        int cc = c - 192;
        int r = cc / 192;
        int o = cc % 192;
        if (o < 64) v = Wrel[((size_t)(r * 64 + i)) * 64 + o];
        else        v = Frel[((size_t)(r * 64 + i)) * 128 + (o - 64)];
    }
    Wcat[i * PCOLS + c] = v;
}

// ---------------- generic tiled SGEMM (encoder only) ----------------
__global__ __launch_bounds__(256)
void sgemm(const float* __restrict__ A, const float* __restrict__ B,
           float* __restrict__ C, int N, int K, int M,
           const float* __restrict__ bias) {
    __shared__ float As[64][64];
    __shared__ float Bs[64][64];
    int tid = threadIdx.x;
    int tx = tid & 15, ty = tid >> 4;
    int n0 = blockIdx.y * 64, m0 = blockIdx.x * 64;

    float c[4][4];
    #pragma unroll
    for (int i = 0; i < 4; i++)
        #pragma unroll
        for (int j = 0; j < 4; j++) c[i][j] = 0.f;

    for (int kb = 0; kb < K; kb += 64) {
        #pragma unroll
        for (int i = 0; i < 16; i++) {
            int idx = tid + i * 256;
            int r = idx >> 6, k = idx & 63;
            int n = n0 + r;
            As[r][k] = (n < N) ? A[(size_t)n * K + kb + k] : 0.f;
        }
        #pragma unroll
        for (int i = 0; i < 16; i++) {
            int idx = tid + i * 256;
            int r = idx >> 6, m = idx & 63;
            Bs[r][m] = B[(size_t)(kb + r) * M + m0 + m];
        }
        __syncthreads();
        #pragma unroll 16
        for (int k = 0; k < 64; k++) {
            float4 bv = *reinterpret_cast<const float4*>(&Bs[k][tx * 4]);
            float a0 = As[ty * 4 + 0][k];
            float a1 = As[ty * 4 + 1][k];
            float a2 = As[ty * 4 + 2][k];
            float a3 = As[ty * 4 + 3][k];
            c[0][0] += a0 * bv.x; c[0][1] += a0 * bv.y; c[0][2] += a0 * bv.z; c[0][3] += a0 * bv.w;
            c[1][0] += a1 * bv.x; c[1][1] += a1 * bv.y; c[1][2] += a1 * bv.z; c[1][3] += a1 * bv.w;
            c[2][0] += a2 * bv.x; c[2][1] += a2 * bv.y; c[2][2] += a2 * bv.z; c[2][3] += a2 * bv.w;
            c[3][0] += a3 * bv.x; c[3][1] += a3 * bv.y; c[3][2] += a3 * bv.z; c[3][3] += a3 * bv.w;
        }
        __syncthreads();
    }

    #pragma unroll
    for (int i = 0; i < 4; i++) {
        int n = n0 + ty * 4 + i;
        if (n < N) {
            #pragma unroll
            for (int j = 0; j < 4; j++) {
                int m = m0 + tx * 4 + j;
                float v = c[i][j];
                if (bias) v += bias[m];
                C[(size_t)n * M + m] = v;
            }
        }
    }
}

// ---------------- fused layer GEMM: P[N,960] = A[N,64] @ B[64,960] ----------------
__global__ __launch_bounds__(256)
void film_gemm(const float* __restrict__ A, const float* __restrict__ B,
               float* __restrict__ P, int N) {
    __shared__ float As[64 * 128];   // [k][row]
    __shared__ float Bs[64 * 64];    // [k][col]
    int tid = threadIdx.x;
    int tx = tid & 15;
    int ty = tid >> 4;
    int n0 = blockIdx.x * 128;

    #pragma unroll
    for (int it = 0; it < 8; it++) {
        int idx = (it * 256 + tid) * 4;
        int row = idx >> 6;
        int k   = idx & 63;
        int n = n0 + row;
        float4 v = (n < N) ? *reinterpret_cast<const float4*>(&A[(size_t)n * 64 + k])
                           : make_float4(0.f, 0.f, 0.f, 0.f);
        As[(k + 0) * 128 + row] = v.x;
        As[(k + 1) * 128 + row] = v.y;
        As[(k + 2) * 128 + row] = v.z;
        As[(k + 3) * 128 + row] = v.w;
    }

    for (int c = 0; c < 15; c++) {
        __syncthreads();
        #pragma unroll
        for (int it = 0; it < 4; it++) {
            int idx = it * 256 + tid;
            int k   = idx >> 4;
            int col = (idx & 15) * 4;
            *reinterpret_cast<float4*>(&Bs[k * 64 + col]) =
                *reinterpret_cast<const float4*>(&B[(size_t)k * PCOLS + c * 64 + col]);
        }
        __syncthreads();

        float4 acc0 = make_float4(0.f,0.f,0.f,0.f), acc1 = acc0, acc2 = acc0, acc3 = acc0;
        float4 acc4 = acc0, acc5 = acc0, acc6 = acc0, acc7 = acc0;

        #pragma unroll 8
        for (int k = 0; k < 64; k++) {
            float4 b  = *reinterpret_cast<const float4*>(&Bs[k * 64 + tx * 4]);
            float4 a0 = *reinterpret_cast<const float4*>(&As[k * 128 + ty * 8]);
            float4 a1 = *reinterpret_cast<const float4*>(&As[k * 128 + ty * 8 + 4]);
            acc0.x += a0.x * b.x; acc0.y += a0.x * b.y; acc0.z += a0.x * b.z; acc0.w += a0.x * b.w;
            acc1.x += a0.y * b.x; acc1.y += a0.y * b.y; acc1.z += a0.y * b.z; acc1.w += a0.y * b.w;
            acc2.x += a0.z * b.x; acc2.y += a0.z * b.y; acc2.z += a0.z * b.z; acc2.w += a0.z * b.w;
            acc3.x += a0.w * b.x; acc3.y += a0.w * b.y; acc3.z += a0.w * b.z; acc3.w += a0.w * b.w;
            acc4.x += a1.x * b.x; acc4.y += a1.x * b.y; acc4.z += a1.x * b.z; acc4.w += a1.x * b.w;
            acc5.x += a1.y * b.x; acc5.y += a1.y * b.y; acc5.z += a1.y * b.z; acc5.w += a1.y * b.w;
            acc6.x += a1.z * b.x; acc6.y += a1.z * b.y; acc6.z += a1.z * b.z; acc6.w += a1.z * b.w;
            acc7.x += a1.w * b.x; acc7.y += a1.w * b.y; acc7.z += a1.w * b.z; acc7.w += a1.w * b.w;
        }

        int colBase = c * 64 + tx * 4;
        int nb = n0 + ty * 8;
        float4* accs[8] = {&acc0,&acc1,&acc2,&acc3,&acc4,&acc5,&acc6,&acc7};
        #pragma unroll
        for (int i = 0; i < 8; i++) {
            int n = nb + i;
            if (n < N)
                *reinterpret_cast<float4*>(&P[(size_t)n * PCOLS + colBase]) = *accs[i];
        }
    }
}

// ---------------- fused FiLM aggregation: one warp per dst node ----------------
// acc = relu(gamma_s*hW + beta_s) + sum_r inv_r * sum_{e in seg(d,r)} relu(g_r*h_r[src]+b_r)
// mode 0: write h = relu(acc*bnscale + bnbias)    (layer 0)
// mode 1: atomicAdd into pool[batch[d]]           (layer 1)
__global__ __launch_bounds__(256)
void film_agg(const float* __restrict__ P, const int* __restrict__ off,
              const int* __restrict__ srcs, const float* __restrict__ inv,
              const float* __restrict__ bng, const float* __restrict__ bnb,
              const int* __restrict__ batch,
              float* __restrict__ hout, float* __restrict__ pool, int mode) {
    int node = blockIdx.x * 8 + (threadIdx.x >> 5);
    if (node >= Nn) return;
    int lane = threadIdx.x & 31;

    const float2* row = reinterpret_cast<const float2*>(P + (size_t)node * PCOLS);
    float2 hw = __ldg(&row[lane]);
    float2 bs = __ldg(&row[32 + lane]);
    float2 gs = __ldg(&row[64 + lane]);
    float ax = fmaxf(gs.x * hw.x + bs.x, 0.f);
    float ay = fmaxf(gs.y * hw.y + bs.y, 0.f);

    #pragma unroll
    for (int r = 0; r < Rr; r++) {
        int key = node * Rr + r;
        int beg = __ldg(&off[key]);
        int end = __ldg(&off[key + 1]);
        if (beg == end) continue;
        float ic = __ldg(&inv[key]);
        float2 br = __ldg(&row[128 + r * 96 + lane]);   // cols 192+192r+64.. as float2
        float2 gr = __ldg(&row[160 + r * 96 + lane]);   // cols 192+192r+128.. as float2
        int hbase2 = 96 + r * 96;                        // float2 idx of h_rel block
        float sx = 0.f, sy = 0.f;
        int e = beg;
        for (; e + 1 < end; e += 2) {
            int s0 = __ldg(&srcs[e]);
            int s1 = __ldg(&srcs[e + 1]);
            float2 h0 = __ldg(reinterpret_cast<const float2*>(P + (size_t)s0 * PCOLS) + hbase2 + lane);
            float2 h1 = __ldg(reinterpret_cast<const float2*>(P + (size_t)s1 * PCOLS) + hbase2 + lane);
            sx += fmaxf(gr.x * h0.x + br.x, 0.f) + fmaxf(gr.x * h1.x + br.x, 0.f);
            sy += fmaxf(gr.y * h0.y + br.y, 0.f) + fmaxf(gr.y * h1.y + br.y, 0.f);
        }
        if (e < end) {
            int s0 = __ldg(&srcs[e]);
            float2 h0 = __ldg(reinterpret_cast<const float2*>(P + (size_t)s0 * PCOLS) + hbase2 + lane);
            sx += fmaxf(gr.x * h0.x + br.x, 0.f);
            sy += fmaxf(gr.y * h0.y + br.y, 0.f);
        }
        ax += sx * ic;
        ay += sy * ic;
    }

    int c0 = 2 * lane;
    if (mode == 0) {
        float k = rsqrtf(1.0f + 1e-5f);
        float ox = fmaxf(ax * (__ldg(&bng[c0])     * k) + __ldg(&bnb[c0]),     0.f);
        float oy = fmaxf(ay * (__ldg(&bng[c0 + 1]) * k) + __ldg(&bnb[c0 + 1]), 0.f);
        *reinterpret_cast<float2*>(&hout[(size_t)node * Hh + c0]) = make_float2(ox, oy);
    } else {
        int g = __ldg(&batch[node]);
        atomicAdd(&pool[g * Hh + c0],     ax);
        atomicAdd(&pool[g * Hh + c0 + 1], ay);
    }
}

// ---------------- head ----------------
__global__ void head1(const float* __restrict__ pool, const float* __restrict__ W,
                      const float* __restrict__ b, float* __restrict__ t) {
    int idx = blockIdx.x * blockDim.x + threadIdx.x;
    if (idx >= Gg * Hh) return;
    int r = idx >> 6, o = idx & 63;
    float s = 0.f;
    #pragma unroll 8
    for (int k = 0; k < Hh; k++) s += pool[r * Hh + k] * W[k * Hh + o];
    t[idx] = fmaxf(s + b[o], 0.f);
}
__global__ void head2(const float* __restrict__ t, const float* __restrict__ W,
                      const float* __restrict__ b, float* __restrict__ out) {
    int idx = blockIdx.x * blockDim.x + threadIdx.x;
    if (idx >= Gg * OUTD) return;
    int r = idx / OUTD, o = idx % OUTD;
    float s = 0.f;
    #pragma unroll 8
    for (int k = 0; k < Hh; k++) s += t[r * Hh + k] * W[k * OUTD + o];
    out[idx] = s + b[o];
}

// ---------------- launch ----------------
extern "C" void kernel_launch(void* const* d_in, const int* in_sizes, int n_in,
                              void* d_out, int out_size) {
    const float* x      = (const float*)d_in[0];
    const int*   ei     = (const int*)  d_in[1];
    const int*   etype  = (const int*)  d_in[2];
    const int*   batch  = (const int*)  d_in[3];
    const float* enc_W  = (const float*)d_in[4];
    const float* enc_b  = (const float*)d_in[5];
    const float* Wskip0 = (const float*)d_in[6];
    const float* Fskip0 = (const float*)d_in[7];
    const float* Wrel0  = (const float*)d_in[8];
    const float* Frel0  = (const float*)d_in[9];
    const float* Wskip1 = (const float*)d_in[10];
    const float* Fskip1 = (const float*)d_in[11];
    const float* Wrel1  = (const float*)d_in[12];
    const float* Frel1  = (const float*)d_in[13];
    const float* bn_g   = (const float*)d_in[14];
    const float* bn_b   = (const float*)d_in[15];
    const float* lin_W  = (const float*)d_in[16];
    const float* lin_b  = (const float*)d_in[17];
    const float* clf_W  = (const float*)d_in[18];
    const float* clf_b  = (const float*)d_in[19];
    float* out = (float*)d_out;

    float *pH, *pP, *pInv, *pWcat, *pPool, *pT;
    int *pCnt, *pOff, *pFill, *pBsum, *pSrcs;
    cudaGetSymbolAddress((void**)&pH,    g_h);
    cudaGetSymbolAddress((void**)&pP,    g_P4);
    cudaGetSymbolAddress((void**)&pCnt,  g_cnt);
    cudaGetSymbolAddress((void**)&pInv,  g_inv);
    cudaGetSymbolAddress((void**)&pOff,  g_off);
    cudaGetSymbolAddress((void**)&pFill, g_fill);
    cudaGetSymbolAddress((void**)&pBsum, g_bsum);
    cudaGetSymbolAddress((void**)&pSrcs, g_srcs);
    cudaGetSymbolAddress((void**)&pWcat, g_Wcat);
    cudaGetSymbolAddress((void**)&pPool, g_pool);
    cudaGetSymbolAddress((void**)&pT,    g_t);

    const int NT = 256;
    int gemmBlocks = (Nn + 127) / 128;
    int aggBlocks  = (Nn + 7) / 8;

    // ---- CSR build (layer-invariant) ----
    zero_i<<<(RN + NT - 1) / NT, NT>>>(pCnt, RN);
    count_edges<<<(Ee + 511) / 512, 512>>>(ei, etype, pCnt);
    inv_counts<<<(RN + NT - 1) / NT, NT>>>(pCnt, pInv);
    scan1<<<NBLK, SCAN_B>>>(pCnt, pOff, pBsum);
    scan2<<<1, 512>>>(pBsum, NBLK);
    scan3<<<(RN + NT - 1) / NT, NT>>>(pOff, pBsum);
    zero_i<<<(RN + NT - 1) / NT, NT>>>(pFill, RN);
    scatter_edges<<<(Ee + 511) / 512, 512>>>(ei, etype, pOff, pFill, pSrcs);

    // Encoder: h = x @ enc_W + enc_b
    {
        dim3 grid(1, (Nn + 63) / 64);
        sgemm<<<grid, 256>>>(x, enc_W, pH, Nn, IND, Hh, enc_b);
    }

    // ---- FiLMConv layer 0 (+ fused BN/ReLU) ----
    repack<<<(64 * PCOLS + NT - 1) / NT, NT>>>(Wskip0, Fskip0, Wrel0, Frel0, pWcat);
    film_gemm<<<gemmBlocks, 256>>>(pH, pWcat, pP, Nn);
    film_agg<<<aggBlocks, 256>>>(pP, pOff, pSrcs, pInv, bn_g, bn_b, batch,
                                 pH, pPool, 0);

    // ---- FiLMConv layer 1 (+ fused global_add_pool) ----
    zero_f<<<(Gg * Hh + NT - 1) / NT, NT>>>(pPool, Gg * Hh);
    repack<<<(64 * PCOLS + NT - 1) / NT, NT>>>(Wskip1, Fskip1, Wrel1, Frel1, pWcat);
    film_gemm<<<gemmBlocks, 256>>>(pH, pWcat, pP, Nn);
    film_agg<<<aggBlocks, 256>>>(pP, pOff, pSrcs, pInv, bn_g, bn_b, batch,
                                 pH, pPool, 1);

    // ---- head ----
    head1<<<(Gg * Hh + NT - 1) / NT, NT>>>(pPool, lin_W, lin_b, pT);
    head2<<<(Gg * OUTD + NT - 1) / NT, NT>>>(pT, clf_W, clf_b, out);
}

// round 8
// speedup vs baseline: 1.3699x; 1.0116x over previous
#include <cuda_runtime.h>
#include <cuda_bf16.h>
#include <math.h>

// Problem constants
#define Nn   100000
#define Ee   1600000
#define IND  128
#define Hh   64
#define Rr   4
#define Gg   128
#define OUTD 10
#define PCOLS 960    // 64 (W_skip) + 128 (F_skip) + 4 * (64 + 128)
#define SKIPC 192    // fp32 skip block cols
#define RELC  768    // bf16 relation block cols
#define RN   (Rr * Nn)
#define SCAN_B 1024
#define NBLK ((RN + SCAN_B - 1) / SCAN_B)

// ---------------- scratch (static __device__ globals: allowed) --------------
__device__ float4        g_P32[(size_t)Nn * SKIPC / 4];  // fp32 skip block [N,192]
__device__ __nv_bfloat162 g_Pb[(size_t)Nn * RELC / 2];   // bf16 relation block [N,768]
__device__ float  g_h  [(size_t)Nn * Hh];
__device__ int    g_cnt [RN];
__device__ float  g_inv [RN];
__device__ int    g_off [RN + 1];
__device__ int    g_fill[RN];
__device__ int    g_bsum[512];
__device__ int    g_srcs[Ee];
__device__ float  g_Wcat[64 * PCOLS];
__device__ float  g_pool[Gg * Hh];
__device__ float  g_t   [Gg * Hh];

// ---------------- small utility kernels ----------------
__global__ void zero_i(int* p, int n) {
    int i = blockIdx.x * blockDim.x + threadIdx.x;
    if (i < n) p[i] = 0;
}
__global__ void zero_f(float* p, int n) {
    int i = blockIdx.x * blockDim.x + threadIdx.x;
    if (i < n) p[i] = 0.f;
}

__global__ void count_edges(const int* __restrict__ ei, const int* __restrict__ et,
                            int* __restrict__ cnt) {
    int e = blockIdx.x * blockDim.x + threadIdx.x;
    if (e < Ee) {
        int d = __ldg(&ei[Ee + e]);
        int r = __ldg(&et[e]);
        atomicAdd(&cnt[d * Rr + r], 1);
    }
}

__global__ void inv_counts(const int* __restrict__ cnt, float* __restrict__ inv) {
    int i = blockIdx.x * blockDim.x + threadIdx.x;
    if (i < RN) {
        int c = cnt[i];
        inv[i] = 1.0f / (float)(c > 0 ? c : 1);
    }
}

// ---------------- exclusive scan (3-kernel) over cnt -> off ----------------
__global__ void scan1(const int* __restrict__ cnt, int* __restrict__ off,
                      int* __restrict__ bsum) {
    __shared__ int sh[SCAN_B];
    int t = threadIdx.x;
    int i = blockIdx.x * SCAN_B + t;
    int v = (i < RN) ? cnt[i] : 0;
    sh[t] = v;
    __syncthreads();
    for (int d = 1; d < SCAN_B; d <<= 1) {
        int x = (t >= d) ? sh[t - d] : 0;
        __syncthreads();
        sh[t] += x;
        __syncthreads();
    }
    if (i < RN) off[i] = sh[t] - v;
    if (t == SCAN_B - 1) bsum[blockIdx.x] = sh[t];
}
__global__ void scan2(int* __restrict__ bsum, int n) {
    __shared__ int sh[512];
    int t = threadIdx.x;
    int v = (t < n) ? bsum[t] : 0;
    sh[t] = v;
    __syncthreads();
    for (int d = 1; d < 512; d <<= 1) {
        int x = (t >= d) ? sh[t - d] : 0;
        __syncthreads();
        sh[t] += x;
        __syncthreads();
    }
    if (t < n) bsum[t] = sh[t] - v;   // exclusive
}
__global__ void scan3(int* __restrict__ off, const int* __restrict__ bsum) {
    int i = blockIdx.x * blockDim.x + threadIdx.x;
    if (i < RN) off[i] += bsum[i / SCAN_B];
    if (i == 0) off[RN] = Ee;
}

// ---------------- scatter edges into CSR (src only) ----------------
__global__ void scatter_edges(const int* __restrict__ ei, const int* __restrict__ et,
                              const int* __restrict__ off, int* __restrict__ fill,
                              int* __restrict__ srcs) {
    int e = blockIdx.x * blockDim.x + threadIdx.x;
    if (e >= Ee) return;
    int d = __ldg(&ei[Ee + e]);
    int r = __ldg(&et[e]);
    int key = d * Rr + r;
    int pos = off[key] + atomicAdd(&fill[key], 1);
    srcs[pos] = __ldg(&ei[e]);
}

// Pack layer weights into Wcat [64 rows (i)] x [960 cols]
__global__ void repack(const float* __restrict__ Wskip, const float* __restrict__ Fskip,
                       const float* __restrict__ Wrel,  const float* __restrict__ Frel,
                       float* __restrict__ Wcat) {
    int idx = blockIdx.x * blockDim.x + threadIdx.x;
    if (idx >= 64 * PCOLS) return;
    int i = idx / PCOLS;
    int c = idx % PCOLS;
    float v;
    if (c < 64) {
        v = Wskip[i * 64 + c];
    } else if (c < 192) {
        v = Fskip[i * 128 + (c - 64)];
    } else {
        int cc = c - 192;
        int r = cc / 192;
        int o = cc % 192;
        if (o < 64) v = Wrel[((size_t)(r * 64 + i)) * 64 + o];
        else        v = Frel[((size_t)(r * 64 + i)) * 128 + (o - 64)];
    }
    Wcat[i * PCOLS + c] = v;
}

// ---------------- generic tiled SGEMM (encoder only) ----------------
__global__ __launch_bounds__(256)
void sgemm(const float* __restrict__ A, const float* __restrict__ B,
           float* __restrict__ C, int N, int K, int M,
           const float* __restrict__ bias) {
    __shared__ float As[64][64];
    __shared__ float Bs[64][64];
    int tid = threadIdx.x;
    int tx = tid & 15, ty = tid >> 4;
    int n0 = blockIdx.y * 64, m0 = blockIdx.x * 64;

    float c[4][4];
    #pragma unroll
    for (int i = 0; i < 4; i++)
        #pragma unroll
        for (int j = 0; j < 4; j++) c[i][j] = 0.f;

    for (int kb = 0; kb < K; kb += 64) {
        #pragma unroll
        for (int i = 0; i < 16; i++) {
            int idx = tid + i * 256;
            int r = idx >> 6, k = idx & 63;
            int n = n0 + r;
            As[r][k] = (n < N) ? A[(size_t)n * K + kb + k] : 0.f;
        }
        #pragma unroll
        for (int i = 0; i < 16; i++) {
            int idx = tid + i * 256;
            int r = idx >> 6, m = idx & 63;
            Bs[r][m] = B[(size_t)(kb + r) * M + m0 + m];
        }
        __syncthreads();
        #pragma unroll 16
        for (int k = 0; k < 64; k++) {
            float4 bv = *reinterpret_cast<const float4*>(&Bs[k][tx * 4]);
            float a0 = As[ty * 4 + 0][k];
            float a1 = As[ty * 4 + 1][k];
            float a2 = As[ty * 4 + 2][k];
            float a3 = As[ty * 4 + 3][k];
            c[0][0] += a0 * bv.x; c[0][1] += a0 * bv.y; c[0][2] += a0 * bv.z; c[0][3] += a0 * bv.w;
            c[1][0] += a1 * bv.x; c[1][1] += a1 * bv.y; c[1][2] += a1 * bv.z; c[1][3] += a1 * bv.w;
            c[2][0] += a2 * bv.x; c[2][1] += a2 * bv.y; c[2][2] += a2 * bv.z; c[2][3] += a2 * bv.w;
            c[3][0] += a3 * bv.x; c[3][1] += a3 * bv.y; c[3][2] += a3 * bv.z; c[3][3] += a3 * bv.w;
        }
        __syncthreads();
    }

    #pragma unroll
    for (int i = 0; i < 4; i++) {
        int n = n0 + ty * 4 + i;
        if (n < N) {
            #pragma unroll
            for (int j = 0; j < 4; j++) {
                int m = m0 + tx * 4 + j;
                float v = c[i][j];
                if (bias) v += bias[m];
                C[(size_t)n * M + m] = v;
            }
        }
    }
}

// ---------------- fused layer GEMM: [N,64] @ [64,960] -> P32 fp32 / Pb bf16 ----
__global__ __launch_bounds__(256)
void film_gemm(const float* __restrict__ A, const float* __restrict__ B,
               float* __restrict__ P32, __nv_bfloat16* __restrict__ Pb, int N) {
    __shared__ float As[64 * 128];   // [k][row]
    __shared__ float Bs[64 * 64];    // [k][col]
    int tid = threadIdx.x;
    int tx = tid & 15;
    int ty = tid >> 4;
    int n0 = blockIdx.x * 128;

    #pragma unroll
    for (int it = 0; it < 8; it++) {
        int idx = (it * 256 + tid) * 4;
        int row = idx >> 6;
        int k   = idx & 63;
        int n = n0 + row;
        float4 v = (n < N) ? *reinterpret_cast<const float4*>(&A[(size_t)n * 64 + k])
                           : make_float4(0.f, 0.f, 0.f, 0.f);
        As[(k + 0) * 128 + row] = v.x;
        As[(k + 1) * 128 + row] = v.y;
        As[(k + 2) * 128 + row] = v.z;
        As[(k + 3) * 128 + row] = v.w;
    }

    for (int c = 0; c < 15; c++) {
        __syncthreads();
        #pragma unroll
        for (int it = 0; it < 4; it++) {
            int idx = it * 256 + tid;
            int k   = idx >> 4;
            int col = (idx & 15) * 4;
            *reinterpret_cast<float4*>(&Bs[k * 64 + col]) =
                *reinterpret_cast<const float4*>(&B[(size_t)k * PCOLS + c * 64 + col]);
        }
        __syncthreads();

        float4 acc0 = make_float4(0.f,0.f,0.f,0.f), acc1 = acc0, acc2 = acc0, acc3 = acc0;
        float4 acc4 = acc0, acc5 = acc0, acc6 = acc0, acc7 = acc0;

        #pragma unroll 8
        for (int k = 0; k < 64; k++) {
            float4 b  = *reinterpret_cast<const float4*>(&Bs[k * 64 + tx * 4]);
            float4 a0 = *reinterpret_cast<const float4*>(&As[k * 128 + ty * 8]);
            float4 a1 = *reinterpret_cast<const float4*>(&As[k * 128 + ty * 8 + 4]);
            acc0.x += a0.x * b.x; acc0.y += a0.x * b.y; acc0.z += a0.x * b.z; acc0.w += a0.x * b.w;
            acc1.x += a0.y * b.x; acc1.y += a0.y * b.y; acc1.z += a0.y * b.z; acc1.w += a0.y * b.w;
            acc2.x += a0.z * b.x; acc2.y += a0.z * b.y; acc2.z += a0.z * b.z; acc2.w += a0.z * b.w;
            acc3.x += a0.w * b.x; acc3.y += a0.w * b.y; acc3.z += a0.w * b.z; acc3.w += a0.w * b.w;
            acc4.x += a1.x * b.x; acc4.y += a1.x * b.y; acc4.z += a1.x * b.z; acc4.w += a1.x * b.w;
            acc5.x += a1.y * b.x; acc5.y += a1.y * b.y; acc5.z += a1.y * b.z; acc5.w += a1.y * b.w;
            acc6.x += a1.z * b.x; acc6.y += a1.z * b.y; acc6.z += a1.z * b.z; acc6.w += a1.z * b.w;
            acc7.x += a1.w * b.x; acc7.y += a1.w * b.y; acc7.z += a1.w * b.z; acc7.w += a1.w * b.w;
        }

        int nb = n0 + ty * 8;
        float4* accs[8] = {&acc0,&acc1,&acc2,&acc3,&acc4,&acc5,&acc6,&acc7};
        if (c < 3) {
            int colBase = c * 64 + tx * 4;
            #pragma unroll
            for (int i = 0; i < 8; i++) {
                int n = nb + i;
                if (n < N)
                    *reinterpret_cast<float4*>(&P32[(size_t)n * SKIPC + colBase]) = *accs[i];
            }
        } else {
            int colBase = c * 64 + tx * 4 - SKIPC;
            #pragma unroll
            for (int i = 0; i < 8; i++) {
                int n = nb + i;
                if (n < N) {
                    float4 a = *accs[i];
                    __nv_bfloat162 lo = __float22bfloat162_rn(make_float2(a.x, a.y));
                    __nv_bfloat162 hi = __float22bfloat162_rn(make_float2(a.z, a.w));
                    uint2 pk;
                    pk.x = *reinterpret_cast<unsigned int*>(&lo);
                    pk.y = *reinterpret_cast<unsigned int*>(&hi);
                    *reinterpret_cast<uint2*>(&Pb[(size_t)n * RELC + colBase]) = pk;
                }
            }
        }
    }
}

// ---------------- fused FiLM aggregation: one warp per dst node ----------------
__global__ __launch_bounds__(256)
void film_agg(const float* __restrict__ P32, const __nv_bfloat16* __restrict__ Pb,
              const int* __restrict__ off, const int* __restrict__ srcs,
              const float* __restrict__ inv,
              const float* __restrict__ bng, const float* __restrict__ bnb,
              const int* __restrict__ batch,
              float* __restrict__ hout, float* __restrict__ pool, int mode) {
    int node = blockIdx.x * 8 + (threadIdx.x >> 5);
    if (node >= Nn) return;
    int lane = threadIdx.x & 31;

    const float2* row32 = reinterpret_cast<const float2*>(P32 + (size_t)node * SKIPC);
    float2 hw = __ldg(&row32[lane]);
    float2 bs = __ldg(&row32[32 + lane]);
    float2 gs = __ldg(&row32[64 + lane]);
    float ax = fmaxf(gs.x * hw.x + bs.x, 0.f);
    float ay = fmaxf(gs.y * hw.y + bs.y, 0.f);

    const __nv_bfloat162* rowb =
        reinterpret_cast<const __nv_bfloat162*>(Pb + (size_t)node * RELC);

    #pragma unroll
    for (int r = 0; r < Rr; r++) {
        int key = node * Rr + r;
        int beg = __ldg(&off[key]);
        int end = __ldg(&off[key + 1]);
        if (beg == end) continue;
        float ic = __ldg(&inv[key]);
        float2 br = __bfloat1622float2(__ldg(&rowb[r * 96 + 32 + lane]));  // cols r*192+64
        float2 gr = __bfloat1622float2(__ldg(&rowb[r * 96 + 64 + lane]));  // cols r*192+128
        int hoff = r * 96 + lane;   // bf162 index of h_rel block element for this lane
        float sx = 0.f, sy = 0.f;
        int e = beg;
        for (; e + 3 < end; e += 4) {
            int s0 = __ldg(&srcs[e]);
            int s1 = __ldg(&srcs[e + 1]);
            int s2 = __ldg(&srcs[e + 2]);
            int s3 = __ldg(&srcs[e + 3]);
            float2 h0 = __bfloat1622float2(__ldg(
                reinterpret_cast<const __nv_bfloat162*>(Pb + (size_t)s0 * RELC) + hoff));
            float2 h1 = __bfloat1622float2(__ldg(
                reinterpret_cast<const __nv_bfloat162*>(Pb + (size_t)s1 * RELC) + hoff));
            float2 h2 = __bfloat1622float2(__ldg(
                reinterpret_cast<const __nv_bfloat162*>(Pb + (size_t)s2 * RELC) + hoff));
            float2 h3 = __bfloat1622float2(__ldg(
                reinterpret_cast<const __nv_bfloat162*>(Pb + (size_t)s3 * RELC) + hoff));
            sx += fmaxf(gr.x * h0.x + br.x, 0.f) + fmaxf(gr.x * h1.x + br.x, 0.f)
                + fmaxf(gr.x * h2.x + br.x, 0.f) + fmaxf(gr.x * h3.x + br.x, 0.f);
            sy += fmaxf(gr.y * h0.y + br.y, 0.f) + fmaxf(gr.y * h1.y + br.y, 0.f)
                + fmaxf(gr.y * h2.y + br.y, 0.f) + fmaxf(gr.y * h3.y + br.y, 0.f);
        }
        for (; e < end; e++) {
            int s0 = __ldg(&srcs[e]);
            float2 h0 = __bfloat1622float2(__ldg(
                reinterpret_cast<const __nv_bfloat162*>(Pb + (size_t)s0 * RELC) + hoff));
            sx += fmaxf(gr.x * h0.x + br.x, 0.f);
            sy += fmaxf(gr.y * h0.y + br.y, 0.f);
        }
        ax += sx * ic;
        ay += sy * ic;
    }

    int c0 = 2 * lane;
    if (mode == 0) {
        float k = rsqrtf(1.0f + 1e-5f);
        float ox = fmaxf(ax * (__ldg(&bng[c0])     * k) + __ldg(&bnb[c0]),     0.f);
        float oy = fmaxf(ay * (__ldg(&bng[c0 + 1]) * k) + __ldg(&bnb[c0 + 1]), 0.f);
        *reinterpret_cast<float2*>(&hout[(size_t)node * Hh + c0]) = make_float2(ox, oy);
    } else {
        int g = __ldg(&batch[node]);
        atomicAdd(&pool[g * Hh + c0],     ax);
        atomicAdd(&pool[g * Hh + c0 + 1], ay);
    }
}

// ---------------- head ----------------
__global__ void head1(const float* __restrict__ pool, const float* __restrict__ W,
                      const float* __restrict__ b, float* __restrict__ t) {
    int idx = blockIdx.x * blockDim.x + threadIdx.x;
    if (idx >= Gg * Hh) return;
    int r = idx >> 6, o = idx & 63;
    float s = 0.f;
    #pragma unroll 8
    for (int k = 0; k < Hh; k++) s += pool[r * Hh + k] * W[k * Hh + o];
    t[idx] = fmaxf(s + b[o], 0.f);
}
__global__ void head2(const float* __restrict__ t, const float* __restrict__ W,
                      const float* __restrict__ b, float* __restrict__ out) {
    int idx = blockIdx.x * blockDim.x + threadIdx.x;
    if (idx >= Gg * OUTD) return;
    int r = idx / OUTD, o = idx % OUTD;
    float s = 0.f;
    #pragma unroll 8
    for (int k = 0; k < Hh; k++) s += t[r * Hh + k] * W[k * OUTD + o];
    out[idx] = s + b[o];
}

// ---------------- launch ----------------
extern "C" void kernel_launch(void* const* d_in, const int* in_sizes, int n_in,
                              void* d_out, int out_size) {
    const float* x      = (const float*)d_in[0];
    const int*   ei     = (const int*)  d_in[1];
    const int*   etype  = (const int*)  d_in[2];
    const int*   batch  = (const int*)  d_in[3];
    const float* enc_W  = (const float*)d_in[4];
    const float* enc_b  = (const float*)d_in[5];
    const float* Wskip0 = (const float*)d_in[6];
    const float* Fskip0 = (const float*)d_in[7];
    const float* Wrel0  = (const float*)d_in[8];
    const float* Frel0  = (const float*)d_in[9];
    const float* Wskip1 = (const float*)d_in[10];
    const float* Fskip1 = (const float*)d_in[11];
    const float* Wrel1  = (const float*)d_in[12];
    const float* Frel1  = (const float*)d_in[13];
    const float* bn_g   = (const float*)d_in[14];
    const float* bn_b   = (const float*)d_in[15];
    const float* lin_W  = (const float*)d_in[16];
    const float* lin_b  = (const float*)d_in[17];
    const float* clf_W  = (const float*)d_in[18];
    const float* clf_b  = (const float*)d_in[19];
    float* out = (float*)d_out;

    float *pH, *pP32, *pInv, *pWcat, *pPool, *pT;
    __nv_bfloat16* pPb;
    int *pCnt, *pOff, *pFill, *pBsum, *pSrcs;
    cudaGetSymbolAddress((void**)&pH,    g_h);
    cudaGetSymbolAddress((void**)&pP32,  g_P32);
    cudaGetSymbolAddress((void**)&pPb,   g_Pb);
    cudaGetSymbolAddress((void**)&pCnt,  g_cnt);
    cudaGetSymbolAddress((void**)&pInv,  g_inv);
    cudaGetSymbolAddress((void**)&pOff,  g_off);
    cudaGetSymbolAddress((void**)&pFill, g_fill);
    cudaGetSymbolAddress((void**)&pBsum, g_bsum);
    cudaGetSymbolAddress((void**)&pSrcs, g_srcs);
    cudaGetSymbolAddress((void**)&pWcat, g_Wcat);
    cudaGetSymbolAddress((void**)&pPool, g_pool);
    cudaGetSymbolAddress((void**)&pT,    g_t);

    const int NT = 256;
    int gemmBlocks = (Nn + 127) / 128;
    int aggBlocks  = (Nn + 7) / 8;

    // ---- CSR build (layer-invariant) ----
    zero_i<<<(RN + NT - 1) / NT, NT>>>(pCnt, RN);
    count_edges<<<(Ee + 511) / 512, 512>>>(ei, etype, pCnt);
    inv_counts<<<(RN + NT - 1) / NT, NT>>>(pCnt, pInv);
    scan1<<<NBLK, SCAN_B>>>(pCnt, pOff, pBsum);
    scan2<<<1, 512>>>(pBsum, NBLK);
    scan3<<<(RN + NT - 1) / NT, NT>>>(pOff, pBsum);
    zero_i<<<(RN + NT - 1) / NT, NT>>>(pFill, RN);
    scatter_edges<<<(Ee + 511) / 512, 512>>>(ei, etype, pOff, pFill, pSrcs);

    // Encoder: h = x @ enc_W + enc_b
    {
        dim3 grid(1, (Nn + 63) / 64);
        sgemm<<<grid, 256>>>(x, enc_W, pH, Nn, IND, Hh, enc_b);
    }

    // ---- FiLMConv layer 0 (+ fused BN/ReLU) ----
    repack<<<(64 * PCOLS + NT - 1) / NT, NT>>>(Wskip0, Fskip0, Wrel0, Frel0, pWcat);
    film_gemm<<<gemmBlocks, 256>>>(pH, pWcat, pP32, pPb, Nn);
    film_agg<<<aggBlocks, 256>>>(pP32, pPb, pOff, pSrcs, pInv, bn_g, bn_b, batch,
                                 pH, pPool, 0);

    // ---- FiLMConv layer 1 (+ fused global_add_pool) ----
    zero_f<<<(Gg * Hh + NT - 1) / NT, NT>>>(pPool, Gg * Hh);
    repack<<<(64 * PCOLS + NT - 1) / NT, NT>>>(Wskip1, Fskip1, Wrel1, Frel1, pWcat);
    film_gemm<<<gemmBlocks, 256>>>(pH, pWcat, pP32, pPb, Nn);
    film_agg<<<aggBlocks, 256>>>(pP32, pPb, pOff, pSrcs, pInv, bn_g, bn_b, batch,
                                 pH, pPool, 1);

    // ---- head ----
    head1<<<(Gg * Hh + NT - 1) / NT, NT>>>(pPool, lin_W, lin_b, pT);
    head2<<<(Gg * OUTD + NT - 1) / NT, NT>>>(pT, clf_W, clf_b, out);
}

// round 9
// speedup vs baseline: 1.3776x; 1.0057x over previous
#include <cuda_runtime.h>
#include <cuda_bf16.h>
#include <math.h>

// Problem constants
#define Nn   100000
#define Ee   1600000
#define IND  128
#define Hh   64
#define Rr   4
#define Gg   128
#define OUTD 10
#define PCOLS 960    // 64 (W_skip) + 128 (F_skip) + 4 * (64 + 128)
#define SKIPC 192    // fp32 skip block cols
#define RELC  768    // bf16 relation block cols
#define RN   (Rr * Nn)
#define SCAN_B 1024
#define NBLK ((RN + SCAN_B - 1) / SCAN_B)

// Packed f32x2 FMA (Blackwell sm_100+): d = a*b + d elementwise on 2 floats.
#define FFMA2(d, a, b) \
    asm("fma.rn.f32x2 %0, %1, %2, %0;" : "+l"(d) : "l"(a), "l"(b))
#define PACKDUP(d, f) \
    asm("mov.b64 %0, {%1, %1};" : "=l"(d) : "f"(f))
#define UNPACK2(lo, hi, d) \
    asm("mov.b64 {%0, %1}, %2;" : "=f"(lo), "=f"(hi) : "l"(d))

// ---------------- scratch (static __device__ globals: allowed) --------------
__device__ float4        g_P32[(size_t)Nn * SKIPC / 4];  // fp32 skip block [N,192]
__device__ __nv_bfloat162 g_Pb[(size_t)Nn * RELC / 2];   // bf16 relation block [N,768]
__device__ float  g_h  [(size_t)Nn * Hh];
__device__ int    g_cnt [RN];
__device__ float  g_inv [RN];
__device__ int    g_off [RN + 1];
__device__ int    g_fill[RN];
__device__ int    g_bsum[512];
__device__ int    g_srcs[Ee];
__device__ float  g_Wcat[64 * PCOLS];
__device__ float  g_pool[Gg * Hh];
__device__ float  g_t   [Gg * Hh];

// ---------------- small utility kernels ----------------
__global__ void zero_i(int* p, int n) {
    int i = blockIdx.x * blockDim.x + threadIdx.x;
    if (i < n) p[i] = 0;
}
__global__ void zero_f(float* p, int n) {
    int i = blockIdx.x * blockDim.x + threadIdx.x;
    if (i < n) p[i] = 0.f;
}

__global__ void count_edges(const int* __restrict__ ei, const int* __restrict__ et,
                            int* __restrict__ cnt) {
    int e = blockIdx.x * blockDim.x + threadIdx.x;
    if (e < Ee) {
        int d = __ldg(&ei[Ee + e]);
        int r = __ldg(&et[e]);
        atomicAdd(&cnt[d * Rr + r], 1);
    }
}

__global__ void inv_counts(const int* __restrict__ cnt, float* __restrict__ inv) {
    int i = blockIdx.x * blockDim.x + threadIdx.x;
    if (i < RN) {
        int c = cnt[i];
        inv[i] = 1.0f / (float)(c > 0 ? c : 1);
    }
}

// ---------------- exclusive scan (3-kernel) over cnt -> off ----------------
__global__ void scan1(const int* __restrict__ cnt, int* __restrict__ off,
                      int* __restrict__ bsum) {
    __shared__ int sh[SCAN_B];
    int t = threadIdx.x;
    int i = blockIdx.x * SCAN_B + t;
    int v = (i < RN) ? cnt[i] : 0;
    sh[t] = v;
    __syncthreads();
    for (int d = 1; d < SCAN_B; d <<= 1) {
        int x = (t >= d) ? sh[t - d] : 0;
        __syncthreads();
        sh[t] += x;
        __syncthreads();
    }
    if (i < RN) off[i] = sh[t] - v;
    if (t == SCAN_B - 1) bsum[blockIdx.x] = sh[t];
}
__global__ void scan2(int* __restrict__ bsum, int n) {
    __shared__ int sh[512];
    int t = threadIdx.x;
    int v = (t < n) ? bsum[t] : 0;
    sh[t] = v;
    __syncthreads();
    for (int d = 1; d < 512; d <<= 1) {
        int x = (t >= d) ? sh[t - d] : 0;
        __syncthreads();
        sh[t] += x;
        __syncthreads();
    }
    if (t < n) bsum[t] = sh[t] - v;   // exclusive
}
__global__ void scan3(int* __restrict__ off, const int* __restrict__ bsum) {
    int i = blockIdx.x * blockDim.x + threadIdx.x;
    if (i < RN) off[i] += bsum[i / SCAN_B];
    if (i == 0) off[RN] = Ee;
}

// ---------------- scatter edges into CSR (src only) ----------------
__global__ void scatter_edges(const int* __restrict__ ei, const int* __restrict__ et,
                              const int* __restrict__ off, int* __restrict__ fill,
                              int* __restrict__ srcs) {
    int e = blockIdx.x * blockDim.x + threadIdx.x;
    if (e >= Ee) return;
    int d = __ldg(&ei[Ee + e]);
    int r = __ldg(&et[e]);
    int key = d * Rr + r;
    int pos = off[key] + atomicAdd(&fill[key], 1);
    srcs[pos] = __ldg(&ei[e]);
}

// Pack layer weights into Wcat [64 rows (i)] x [960 cols]
__global__ void repack(const float* __restrict__ Wskip, const float* __restrict__ Fskip,
                       const float* __restrict__ Wrel,  const float* __restrict__ Frel,
                       float* __restrict__ Wcat) {
    int idx = blockIdx.x * blockDim.x + threadIdx.x;
    if (idx >= 64 * PCOLS) return;
    int i = idx / PCOLS;
    int c = idx % PCOLS;
    float v;
    if (c < 64) {
        v = Wskip[i * 64 + c];
    } else if (c < 192) {
        v = Fskip[i * 128 + (c - 64)];
    } else {
        int cc = c - 192;
        int r = cc / 192;
        int o = cc % 192;
        if (o < 64) v = Wrel[((size_t)(r * 64 + i)) * 64 + o];
        else        v = Frel[((size_t)(r * 64 + i)) * 128 + (o - 64)];
    }
    Wcat[i * PCOLS + c] = v;
}

// ---------------- generic tiled SGEMM (encoder only) ----------------
__global__ __launch_bounds__(256)
void sgemm(const float* __restrict__ A, const float* __restrict__ B,
           float* __restrict__ C, int N, int K, int M,
           const float* __restrict__ bias) {
    __shared__ float As[64][64];
    __shared__ float Bs[64][64];
    int tid = threadIdx.x;
    int tx = tid & 15, ty = tid >> 4;
    int n0 = blockIdx.y * 64, m0 = blockIdx.x * 64;

    float c[4][4];
    #pragma unroll
    for (int i = 0; i < 4; i++)
        #pragma unroll
        for (int j = 0; j < 4; j++) c[i][j] = 0.f;

    for (int kb = 0; kb < K; kb += 64) {
        #pragma unroll
        for (int i = 0; i < 16; i++) {
            int idx = tid + i * 256;
            int r = idx >> 6, k = idx & 63;
            int n = n0 + r;
            As[r][k] = (n < N) ? A[(size_t)n * K + kb + k] : 0.f;
        }
        #pragma unroll
        for (int i = 0; i < 16; i++) {
            int idx = tid + i * 256;
            int r = idx >> 6, m = idx & 63;
            Bs[r][m] = B[(size_t)(kb + r) * M + m0 + m];
        }
        __syncthreads();
        #pragma unroll 16
        for (int k = 0; k < 64; k++) {
            float4 bv = *reinterpret_cast<const float4*>(&Bs[k][tx * 4]);
            float a0 = As[ty * 4 + 0][k];
            float a1 = As[ty * 4 + 1][k];
            float a2 = As[ty * 4 + 2][k];
            float a3 = As[ty * 4 + 3][k];
            c[0][0] += a0 * bv.x; c[0][1] += a0 * bv.y; c[0][2] += a0 * bv.z; c[0][3] += a0 * bv.w;
            c[1][0] += a1 * bv.x; c[1][1] += a1 * bv.y; c[1][2] += a1 * bv.z; c[1][3] += a1 * bv.w;
            c[2][0] += a2 * bv.x; c[2][1] += a2 * bv.y; c[2][2] += a2 * bv.z; c[2][3] += a2 * bv.w;
            c[3][0] += a3 * bv.x; c[3][1] += a3 * bv.y; c[3][2] += a3 * bv.z; c[3][3] += a3 * bv.w;
        }
        __syncthreads();
    }

    #pragma unroll
    for (int i = 0; i < 4; i++) {
        int n = n0 + ty * 4 + i;
        if (n < N) {
            #pragma unroll
            for (int j = 0; j < 4; j++) {
                int m = m0 + tx * 4 + j;
                float v = c[i][j];
                if (bias) v += bias[m];
                C[(size_t)n * M + m] = v;
            }
        }
    }
}

// ---------------- fused layer GEMM: [N,64] @ [64,960] -> P32 fp32 / Pb bf16 ----
// Packed f32x2 FMA inner loop: row-pairs packed in 64-bit regs, B duplicated.
__global__ __launch_bounds__(256)
void film_gemm(const float* __restrict__ A, const float* __restrict__ B,
               float* __restrict__ P32, __nv_bfloat16* __restrict__ Pb, int N) {
    __shared__ float As[64 * 128];   // [k][row]  (row-adjacent pairs contiguous)
    __shared__ float Bs[64 * 64];    // [k][col]
    int tid = threadIdx.x;
    int tx = tid & 15;        // column group: 4 cols
    int ty = tid >> 4;        // row group: 8 rows (4 packed pairs)
    int n0 = blockIdx.x * 128;

    #pragma unroll
    for (int it = 0; it < 8; it++) {
        int idx = (it * 256 + tid) * 4;
        int row = idx >> 6;
        int k   = idx & 63;
        int n = n0 + row;
        float4 v = (n < N) ? *reinterpret_cast<const float4*>(&A[(size_t)n * 64 + k])
                           : make_float4(0.f, 0.f, 0.f, 0.f);
        As[(k + 0) * 128 + row] = v.x;
        As[(k + 1) * 128 + row] = v.y;
        As[(k + 2) * 128 + row] = v.z;
        As[(k + 3) * 128 + row] = v.w;
    }

    for (int c = 0; c < 15; c++) {
        __syncthreads();
        #pragma unroll
        for (int it = 0; it < 4; it++) {
            int idx = it * 256 + tid;
            int k   = idx >> 4;
            int col = (idx & 15) * 4;
            *reinterpret_cast<float4*>(&Bs[k * 64 + col]) =
                *reinterpret_cast<const float4*>(&B[(size_t)k * PCOLS + c * 64 + col]);
        }
        __syncthreads();

        // acc[rp][cc]: rp = row-pair (rows ty*8+2rp, ty*8+2rp+1), cc = column
        unsigned long long acc[4][4];
        #pragma unroll
        for (int i = 0; i < 4; i++)
            #pragma unroll
            for (int j = 0; j < 4; j++) acc[i][j] = 0ull;

        #pragma unroll 8
        for (int k = 0; k < 64; k++) {
            float4 b = *reinterpret_cast<const float4*>(&Bs[k * 64 + tx * 4]);
            ulonglong2 aA = *reinterpret_cast<const ulonglong2*>(&As[k * 128 + ty * 8]);
            ulonglong2 aB = *reinterpret_cast<const ulonglong2*>(&As[k * 128 + ty * 8 + 4]);
            unsigned long long bb0, bb1, bb2, bb3;
            PACKDUP(bb0, b.x); PACKDUP(bb1, b.y); PACKDUP(bb2, b.z); PACKDUP(bb3, b.w);
            FFMA2(acc[0][0], aA.x, bb0); FFMA2(acc[0][1], aA.x, bb1);
            FFMA2(acc[0][2], aA.x, bb2); FFMA2(acc[0][3], aA.x, bb3);
            FFMA2(acc[1][0], aA.y, bb0); FFMA2(acc[1][1], aA.y, bb1);
            FFMA2(acc[1][2], aA.y, bb2); FFMA2(acc[1][3], aA.y, bb3);
            FFMA2(acc[2][0], aB.x, bb0); FFMA2(acc[2][1], aB.x, bb1);
            FFMA2(acc[2][2], aB.x, bb2); FFMA2(acc[2][3], aB.x, bb3);
            FFMA2(acc[3][0], aB.y, bb0); FFMA2(acc[3][1], aB.y, bb1);
            FFMA2(acc[3][2], aB.y, bb2); FFMA2(acc[3][3], aB.y, bb3);
        }

        int nb = n0 + ty * 8;
        #pragma unroll
        for (int rp = 0; rp < 4; rp++) {
            float4 ev, ov;
            UNPACK2(ev.x, ov.x, acc[rp][0]);
            UNPACK2(ev.y, ov.y, acc[rp][1]);
            UNPACK2(ev.z, ov.z, acc[rp][2]);
            UNPACK2(ev.w, ov.w, acc[rp][3]);
            int nE = nb + 2 * rp;
            int nO = nE + 1;
            if (c < 3) {
                int colBase = c * 64 + tx * 4;
                if (nE < N) *reinterpret_cast<float4*>(&P32[(size_t)nE * SKIPC + colBase]) = ev;
                if (nO < N) *reinterpret_cast<float4*>(&P32[(size_t)nO * SKIPC + colBase]) = ov;
            } else {
                int colBase = c * 64 + tx * 4 - SKIPC;
                if (nE < N) {
                    __nv_bfloat162 lo = __float22bfloat162_rn(make_float2(ev.x, ev.y));
                    __nv_bfloat162 hi = __float22bfloat162_rn(make_float2(ev.z, ev.w));
                    uint2 pk;
                    pk.x = *reinterpret_cast<unsigned int*>(&lo);
                    pk.y = *reinterpret_cast<unsigned int*>(&hi);
                    *reinterpret_cast<uint2*>(&Pb[(size_t)nE * RELC + colBase]) = pk;
                }
                if (nO < N) {
                    __nv_bfloat162 lo = __float22bfloat162_rn(make_float2(ov.x, ov.y));
                    __nv_bfloat162 hi = __float22bfloat162_rn(make_float2(ov.z, ov.w));
                    uint2 pk;
                    pk.x = *reinterpret_cast<unsigned int*>(&lo);
                    pk.y = *reinterpret_cast<unsigned int*>(&hi);
                    *reinterpret_cast<uint2*>(&Pb[(size_t)nO * RELC + colBase]) = pk;
                }
            }
        }
    }
}

// ---------------- fused FiLM aggregation: one warp per dst node ----------------
__global__ __launch_bounds__(256)
void film_agg(const float* __restrict__ P32, const __nv_bfloat16* __restrict__ Pb,
              const int* __restrict__ off, const int* __restrict__ srcs,
              const float* __restrict__ inv,
              const float* __restrict__ bng, const float* __restrict__ bnb,
              const int* __restrict__ batch,
              float* __restrict__ hout, float* __restrict__ pool, int mode) {
    int node = blockIdx.x * 8 + (threadIdx.x >> 5);
    if (node >= Nn) return;
    int lane = threadIdx.x & 31;

    const float2* row32 = reinterpret_cast<const float2*>(P32 + (size_t)node * SKIPC);
    float2 hw = __ldg(&row32[lane]);
    float2 bs = __ldg(&row32[32 + lane]);
    float2 gs = __ldg(&row32[64 + lane]);
    float ax = fmaxf(gs.x * hw.x + bs.x, 0.f);
    float ay = fmaxf(gs.y * hw.y + bs.y, 0.f);

    const __nv_bfloat162* rowb =
        reinterpret_cast<const __nv_bfloat162*>(Pb + (size_t)node * RELC);

    #pragma unroll
    for (int r = 0; r < Rr; r++) {
        int key = node * Rr + r;
        int beg = __ldg(&off[key]);
        int end = __ldg(&off[key + 1]);
        if (beg == end) continue;
        float ic = __ldg(&inv[key]);
        float2 br = __bfloat1622float2(__ldg(&rowb[r * 96 + 32 + lane]));
        float2 gr = __bfloat1622float2(__ldg(&rowb[r * 96 + 64 + lane]));
        int hoff = r * 96 + lane;
        float sx = 0.f, sy = 0.f;
        int e = beg;
        for (; e + 3 < end; e += 4) {
            int s0 = __ldg(&srcs[e]);
            int s1 = __ldg(&srcs[e + 1]);
            int s2 = __ldg(&srcs[e + 2]);
            int s3 = __ldg(&srcs[e + 3]);
            float2 h0 = __bfloat1622float2(__ldg(
                reinterpret_cast<const __nv_bfloat162*>(Pb + (size_t)s0 * RELC) + hoff));
            float2 h1 = __bfloat1622float2(__ldg(
                reinterpret_cast<const __nv_bfloat162*>(Pb + (size_t)s1 * RELC) + hoff));
            float2 h2 = __bfloat1622float2(__ldg(
                reinterpret_cast<const __nv_bfloat162*>(Pb + (size_t)s2 * RELC) + hoff));
            float2 h3 = __bfloat1622float2(__ldg(
                reinterpret_cast<const __nv_bfloat162*>(Pb + (size_t)s3 * RELC) + hoff));
            sx += fmaxf(gr.x * h0.x + br.x, 0.f) + fmaxf(gr.x * h1.x + br.x, 0.f)
                + fmaxf(gr.x * h2.x + br.x, 0.f) + fmaxf(gr.x * h3.x + br.x, 0.f);
            sy += fmaxf(gr.y * h0.y + br.y, 0.f) + fmaxf(gr.y * h1.y + br.y, 0.f)
                + fmaxf(gr.y * h2.y + br.y, 0.f) + fmaxf(gr.y * h3.y + br.y, 0.f);
        }
        for (; e < end; e++) {
            int s0 = __ldg(&srcs[e]);
            float2 h0 = __bfloat1622float2(__ldg(
                reinterpret_cast<const __nv_bfloat162*>(Pb + (size_t)s0 * RELC) + hoff));
            sx += fmaxf(gr.x * h0.x + br.x, 0.f);
            sy += fmaxf(gr.y * h0.y + br.y, 0.f);
        }
        ax += sx * ic;
        ay += sy * ic;
    }

    int c0 = 2 * lane;
    if (mode == 0) {
        float k = rsqrtf(1.0f + 1e-5f);
        float ox = fmaxf(ax * (__ldg(&bng[c0])     * k) + __ldg(&bnb[c0]),     0.f);
        float oy = fmaxf(ay * (__ldg(&bng[c0 + 1]) * k) + __ldg(&bnb[c0 + 1]), 0.f);
        *reinterpret_cast<float2*>(&hout[(size_t)node * Hh + c0]) = make_float2(ox, oy);
    } else {
        int g = __ldg(&batch[node]);
        atomicAdd(&pool[g * Hh + c0],     ax);
        atomicAdd(&pool[g * Hh + c0 + 1], ay);
    }
}

// ---------------- head ----------------
__global__ void head1(const float* __restrict__ pool, const float* __restrict__ W,
                      const float* __restrict__ b, float* __restrict__ t) {
    int idx = blockIdx.x * blockDim.x + threadIdx.x;
    if (idx >= Gg * Hh) return;
    int r = idx >> 6, o = idx & 63;
    float s = 0.f;
    #pragma unroll 8
    for (int k = 0; k < Hh; k++) s += pool[r * Hh + k] * W[k * Hh + o];
    t[idx] = fmaxf(s + b[o], 0.f);
}
__global__ void head2(const float* __restrict__ t, const float* __restrict__ W,
                      const float* __restrict__ b, float* __restrict__ out) {
    int idx = blockIdx.x * blockDim.x + threadIdx.x;
    if (idx >= Gg * OUTD) return;
    int r = idx / OUTD, o = idx % OUTD;
    float s = 0.f;
    #pragma unroll 8
    for (int k = 0; k < Hh; k++) s += t[r * Hh + k] * W[k * OUTD + o];
    out[idx] = s + b[o];
}

// ---------------- launch ----------------
extern "C" void kernel_launch(void* const* d_in, const int* in_sizes, int n_in,
                              void* d_out, int out_size) {
    const float* x      = (const float*)d_in[0];
    const int*   ei     = (const int*)  d_in[1];
    const int*   etype  = (const int*)  d_in[2];
    const int*   batch  = (const int*)  d_in[3];
    const float* enc_W  = (const float*)d_in[4];
    const float* enc_b  = (const float*)d_in[5];
    const float* Wskip0 = (const float*)d_in[6];
    const float* Fskip0 = (const float*)d_in[7];
    const float* Wrel0  = (const float*)d_in[8];
    const float* Frel0  = (const float*)d_in[9];
    const float* Wskip1 = (const float*)d_in[10];
    const float* Fskip1 = (const float*)d_in[11];
    const float* Wrel1  = (const float*)d_in[12];
    const float* Frel1  = (const float*)d_in[13];
    const float* bn_g   = (const float*)d_in[14];
    const float* bn_b   = (const float*)d_in[15];
    const float* lin_W  = (const float*)d_in[16];
    const float* lin_b  = (const float*)d_in[17];
    const float* clf_W  = (const float*)d_in[18];
    const float* clf_b  = (const float*)d_in[19];
    float* out = (float*)d_out;

    float *pH, *pP32, *pInv, *pWcat, *pPool, *pT;
    __nv_bfloat16* pPb;
    int *pCnt, *pOff, *pFill, *pBsum, *pSrcs;
    cudaGetSymbolAddress((void**)&pH,    g_h);
    cudaGetSymbolAddress((void**)&pP32,  g_P32);
    cudaGetSymbolAddress((void**)&pPb,   g_Pb);
    cudaGetSymbolAddress((void**)&pCnt,  g_cnt);
    cudaGetSymbolAddress((void**)&pInv,  g_inv);
    cudaGetSymbolAddress((void**)&pOff,  g_off);
    cudaGetSymbolAddress((void**)&pFill, g_fill);
    cudaGetSymbolAddress((void**)&pBsum, g_bsum);
    cudaGetSymbolAddress((void**)&pSrcs, g_srcs);
    cudaGetSymbolAddress((void**)&pWcat, g_Wcat);
    cudaGetSymbolAddress((void**)&pPool, g_pool);
    cudaGetSymbolAddress((void**)&pT,    g_t);

    const int NT = 256;
    int gemmBlocks = (Nn + 127) / 128;
    int aggBlocks  = (Nn + 7) / 8;

    // ---- CSR build (layer-invariant) ----
    zero_i<<<(RN + NT - 1) / NT, NT>>>(pCnt, RN);
    count_edges<<<(Ee + 511) / 512, 512>>>(ei, etype, pCnt);
    inv_counts<<<(RN + NT - 1) / NT, NT>>>(pCnt, pInv);
    scan1<<<NBLK, SCAN_B>>>(pCnt, pOff, pBsum);
    scan2<<<1, 512>>>(pBsum, NBLK);
    scan3<<<(RN + NT - 1) / NT, NT>>>(pOff, pBsum);
    zero_i<<<(RN + NT - 1) / NT, NT>>>(pFill, RN);
    scatter_edges<<<(Ee + 511) / 512, 512>>>(ei, etype, pOff, pFill, pSrcs);

    // Encoder: h = x @ enc_W + enc_b
    {
        dim3 grid(1, (Nn + 63) / 64);
        sgemm<<<grid, 256>>>(x, enc_W, pH, Nn, IND, Hh, enc_b);
    }

    // ---- FiLMConv layer 0 (+ fused BN/ReLU) ----
    repack<<<(64 * PCOLS + NT - 1) / NT, NT>>>(Wskip0, Fskip0, Wrel0, Frel0, pWcat);
    film_gemm<<<gemmBlocks, 256>>>(pH, pWcat, pP32, pPb, Nn);
    film_agg<<<aggBlocks, 256>>>(pP32, pPb, pOff, pSrcs, pInv, bn_g, bn_b, batch,
                                 pH, pPool, 0);

    // ---- FiLMConv layer 1 (+ fused global_add_pool) ----
    zero_f<<<(Gg * Hh + NT - 1) / NT, NT>>>(pPool, Gg * Hh);
    repack<<<(64 * PCOLS + NT - 1) / NT, NT>>>(Wskip1, Fskip1, Wrel1, Frel1, pWcat);
    film_gemm<<<gemmBlocks, 256>>>(pH, pWcat, pP32, pPb, Nn);
    film_agg<<<aggBlocks, 256>>>(pP32, pPb, pOff, pSrcs, pInv, bn_g, bn_b, batch,
                                 pH, pPool, 1);

    // ---- head ----
    head1<<<(Gg * Hh + NT - 1) / NT, NT>>>(pPool, lin_W, lin_b, pT);
    head2<<<(Gg * OUTD + NT - 1) / NT, NT>>>(pT, clf_W, clf_b, out);
}

// round 11
// speedup vs baseline: 2.0423x; 1.4825x over previous
#include <cuda_runtime.h>
#include <cuda_bf16.h>
#include <math.h>
#include <stdint.h>

// Problem constants
#define Nn   100000
#define Ee   1600000
#define IND  128
#define Hh   64
#define Rr   4
#define Gg   128
#define OUTD 10
#define PCOLS 960
#define SKIPC 192
#define RELC  768
#define RN   (Rr * Nn)
#define SCAN_B 1024
#define NBLK ((RN + SCAN_B - 1) / SCAN_B)
#define NCHUNK 15

// round fp32 -> tf32-representable fp32
__device__ __forceinline__ float rtf32(float x) {
    uint32_t y;
    asm("cvt.rna.tf32.f32 %0, %1;" : "=r"(y) : "f"(x));
    return __uint_as_float(y);
}

// m16n8k8 tf32 mma, D += A*B (fp32 accum in place)
__device__ __forceinline__ void mma_tf32(float* d, const float* a, float b0, float b1) {
    asm("mma.sync.aligned.m16n8k8.row.col.f32.tf32.tf32.f32 "
        "{%0,%1,%2,%3}, {%4,%5,%6,%7}, {%8,%9}, {%0,%1,%2,%3};"
        : "+f"(d[0]), "+f"(d[1]), "+f"(d[2]), "+f"(d[3])
        : "r"(__float_as_uint(a[0])), "r"(__float_as_uint(a[1])),
          "r"(__float_as_uint(a[2])), "r"(__float_as_uint(a[3])),
          "r"(__float_as_uint(b0)), "r"(__float_as_uint(b1)));
}

// ---------------- scratch ----------------
__device__ float4         g_P32[(size_t)Nn * SKIPC / 4];
__device__ __nv_bfloat162 g_Pb [(size_t)Nn * RELC / 2];
__device__ float  g_h  [(size_t)Nn * Hh];
__device__ int    g_cnt [RN];
__device__ float  g_inv [RN];
__device__ int    g_off [RN + 1];
__device__ int    g_fill[RN];
__device__ int    g_bsum[512];
__device__ int    g_srcs[Ee];
__device__ float2 g_Wp [NCHUNK * 2048];   // paired tf32 B fragments
__device__ float  g_pool[Gg * Hh];
__device__ float  g_t   [Gg * Hh];

// ---------------- small utility kernels ----------------
__global__ void zero_i(int* p, int n) {
    int i = blockIdx.x * blockDim.x + threadIdx.x;
    if (i < n) p[i] = 0;
}
__global__ void zero_f(float* p, int n) {
    int i = blockIdx.x * blockDim.x + threadIdx.x;
    if (i < n) p[i] = 0.f;
}

__global__ void count_edges(const int* __restrict__ ei, const int* __restrict__ et,
                            int* __restrict__ cnt) {
    int e = blockIdx.x * blockDim.x + threadIdx.x;
    if (e < Ee) {
        int d = __ldg(&ei[Ee + e]);
        int r = __ldg(&et[e]);
        atomicAdd(&cnt[d * Rr + r], 1);
    }
}

__global__ void inv_counts(const int* __restrict__ cnt, float* __restrict__ inv) {
    int i = blockIdx.x * blockDim.x + threadIdx.x;
    if (i < RN) {
        int c = cnt[i];
        inv[i] = 1.0f / (float)(c > 0 ? c : 1);
    }
}

// ---------------- exclusive scan ----------------
__global__ void scan1(const int* __restrict__ cnt, int* __restrict__ off,
                      int* __restrict__ bsum) {
    __shared__ int sh[SCAN_B];
    int t = threadIdx.x;
    int i = blockIdx.x * SCAN_B + t;
    int v = (i < RN) ? cnt[i] : 0;
    sh[t] = v;
    __syncthreads();
    for (int d = 1; d < SCAN_B; d <<= 1) {
        int x = (t >= d) ? sh[t - d] : 0;
        __syncthreads();
        sh[t] += x;
        __syncthreads();
    }
    if (i < RN) off[i] = sh[t] - v;
    if (t == SCAN_B - 1) bsum[blockIdx.x] = sh[t];
}
__global__ void scan2(int* __restrict__ bsum, int n) {
    __shared__ int sh[512];
    int t = threadIdx.x;
    int v = (t < n) ? bsum[t] : 0;
    sh[t] = v;
    __syncthreads();
    for (int d = 1; d < 512; d <<= 1) {
        int x = (t >= d) ? sh[t - d] : 0;
        __syncthreads();
        sh[t] += x;
        __syncthreads();
    }
    if (t < n) bsum[t] = sh[t] - v;
}
__global__ void scan3(int* __restrict__ off, const int* __restrict__ bsum) {
    int i = blockIdx.x * blockDim.x + threadIdx.x;
    if (i < RN) off[i] += bsum[i / SCAN_B];
    if (i == 0) off[RN] = Ee;
}

__global__ void scatter_edges(const int* __restrict__ ei, const int* __restrict__ et,
                              const int* __restrict__ off, int* __restrict__ fill,
                              int* __restrict__ srcs) {
    int e = blockIdx.x * blockDim.x + threadIdx.x;
    if (e >= Ee) return;
    int d = __ldg(&ei[Ee + e]);
    int r = __ldg(&et[e]);
    int key = d * Rr + r;
    int pos = off[key] + atomicAdd(&fill[key], 1);
    srcs[pos] = __ldg(&ei[e]);
}

// weight element W[k][c] of the fused [64 x 960] matrix
__device__ __forceinline__ float wcat_val(int k, int c,
        const float* Wskip, const float* Fskip,
        const float* Wrel,  const float* Frel) {
    if (c < 64)  return Wskip[k * 64 + c];
    if (c < 192) return Fskip[k * 128 + (c - 64)];
    int cc = c - 192;
    int r = cc / 192;
    int o = cc % 192;
    if (o < 64) return Wrel[((size_t)(r * 64 + k)) * 64 + o];
    return Frel[((size_t)(r * 64 + k)) * 128 + (o - 64)];
}

// Repack weights into paired tf32 fragment layout:
// Wp[c*2048 + (ks*64+col)*4 + kk] = { W[ks*8+kk][c*64+col], W[ks*8+kk+4][c*64+col] }
__global__ void repack2(const float* __restrict__ Wskip, const float* __restrict__ Fskip,
                        const float* __restrict__ Wrel,  const float* __restrict__ Frel,
                        float2* __restrict__ Wp) {
    int u = blockIdx.x * blockDim.x + threadIdx.x;
    if (u >= NCHUNK * 2048) return;
    int c   = u >> 11;
    int rem = u & 2047;
    int ks  = rem >> 8;
    int rem2 = rem & 255;
    int col = rem2 >> 2;
    int kk  = rem2 & 3;
    int gc = c * 64 + col;
    int k0 = ks * 8 + kk;
    Wp[u] = make_float2(rtf32(wcat_val(k0,     gc, Wskip, Fskip, Wrel, Frel)),
                        rtf32(wcat_val(k0 + 4, gc, Wskip, Fskip, Wrel, Frel)));
}

// ---------------- generic tiled SGEMM (encoder; output rounded to tf32) -------
__global__ __launch_bounds__(256)
void sgemm(const float* __restrict__ A, const float* __restrict__ B,
           float* __restrict__ C, int N, int K, int M,
           const float* __restrict__ bias) {
    __shared__ float As[64][64];
    __shared__ float Bs[64][64];
    int tid = threadIdx.x;
    int tx = tid & 15, ty = tid >> 4;
    int n0 = blockIdx.y * 64, m0 = blockIdx.x * 64;

    float c[4][4];
    #pragma unroll
    for (int i = 0; i < 4; i++)
        #pragma unroll
        for (int j = 0; j < 4; j++) c[i][j] = 0.f;

    for (int kb = 0; kb < K; kb += 64) {
        #pragma unroll
        for (int i = 0; i < 16; i++) {
            int idx = tid + i * 256;
            int r = idx >> 6, k = idx & 63;
            int n = n0 + r;
            As[r][k] = (n < N) ? A[(size_t)n * K + kb + k] : 0.f;
        }
        #pragma unroll
        for (int i = 0; i < 16; i++) {
            int idx = tid + i * 256;
            int r = idx >> 6, m = idx & 63;
            Bs[r][m] = B[(size_t)(kb + r) * M + m0 + m];
        }
        __syncthreads();
        #pragma unroll 16
        for (int k = 0; k < 64; k++) {
            float4 bv = *reinterpret_cast<const float4*>(&Bs[k][tx * 4]);
            float a0 = As[ty * 4 + 0][k];
            float a1 = As[ty * 4 + 1][k];
            float a2 = As[ty * 4 + 2][k];
            float a3 = As[ty * 4 + 3][k];
            c[0][0] += a0 * bv.x; c[0][1] += a0 * bv.y; c[0][2] += a0 * bv.z; c[0][3] += a0 * bv.w;
            c[1][0] += a1 * bv.x; c[1][1] += a1 * bv.y; c[1][2] += a1 * bv.z; c[1][3] += a1 * bv.w;
            c[2][0] += a2 * bv.x; c[2][1] += a2 * bv.y; c[2][2] += a2 * bv.z; c[2][3] += a2 * bv.w;
            c[3][0] += a3 * bv.x; c[3][1] += a3 * bv.y; c[3][2] += a3 * bv.z; c[3][3] += a3 * bv.w;
        }
        __syncthreads();
    }

    #pragma unroll
    for (int i = 0; i < 4; i++) {
        int n = n0 + ty * 4 + i;
        if (n < N) {
            #pragma unroll
            for (int j = 0; j < 4; j++) {
                int m = m0 + tx * 4 + j;
                float v = c[i][j];
                if (bias) v += bias[m];
                C[(size_t)n * M + m] = rtf32(v);   // h feeds tf32 GEMM only
            }
        }
    }
}

// ---------------- tensor-core layer GEMM: [N,64] @ [64,960] -------------------
// 128 threads = 4 warps, 128 rows/block (warp: 2x m16 row tiles).
// A fragments register-resident for all 15 column chunks; B chunk staged in smem
// in paired fragment layout (straight 16KB copy from g_Wp).
__global__ __launch_bounds__(128)
void film_gemm_tc(const float* __restrict__ A, const float2* __restrict__ Wp,
                  float* __restrict__ P32, __nv_bfloat16* __restrict__ Pb, int N) {
    __shared__ float2 Bs[2048];   // 16KB
    int tid = threadIdx.x;
    int w    = tid >> 5;
    int lane = tid & 31;
    int gid  = lane >> 2;   // 0..7
    int tig  = lane & 3;    // 0..3
    int n0 = blockIdx.x * 128;

    // Load A fragments (2 row tiles x 8 k-steps x 4 regs)
    float a[2][8][4];
    #pragma unroll
    for (int t = 0; t < 2; t++) {
        int r0 = n0 + w * 32 + t * 16 + gid;
        int r1 = r0 + 8;
        #pragma unroll
        for (int ks = 0; ks < 8; ks++) {
            int c0 = ks * 8 + tig;
            a[t][ks][0] = (r0 < N) ? __ldg(&A[(size_t)r0 * 64 + c0])     : 0.f;
            a[t][ks][1] = (r1 < N) ? __ldg(&A[(size_t)r1 * 64 + c0])     : 0.f;
            a[t][ks][2] = (r0 < N) ? __ldg(&A[(size_t)r0 * 64 + c0 + 4]) : 0.f;
            a[t][ks][3] = (r1 < N) ? __ldg(&A[(size_t)r1 * 64 + c0 + 4]) : 0.f;
        }
    }

    for (int c = 0; c < NCHUNK; c++) {
        __syncthreads();
        // contiguous copy of 16KB chunk (1024 float4)
        const float4* src = reinterpret_cast<const float4*>(Wp + c * 2048);
        float4* dst = reinterpret_cast<float4*>(Bs);
        #pragma unroll
        for (int i = 0; i < 8; i++)
            dst[tid + i * 128] = __ldg(&src[tid + i * 128]);
        __syncthreads();

        float acc[8][2][4];
        #pragma unroll
        for (int s = 0; s < 8; s++)
            #pragma unroll
            for (int t = 0; t < 2; t++)
                #pragma unroll
                for (int j = 0; j < 4; j++) acc[s][t][j] = 0.f;

        #pragma unroll
        for (int sub = 0; sub < 8; sub++) {
            #pragma unroll
            for (int ks = 0; ks < 8; ks++) {
                float2 b = Bs[(ks * 64 + sub * 8 + gid) * 4 + tig];
                mma_tf32(acc[sub][0], a[0][ks], b.x, b.y);
                mma_tf32(acc[sub][1], a[1][ks], b.x, b.y);
            }
        }

        // epilogue
        #pragma unroll
        for (int sub = 0; sub < 8; sub++) {
            #pragma unroll
            for (int t = 0; t < 2; t++) {
                int r0 = n0 + w * 32 + t * 16 + gid;
                int r1 = r0 + 8;
                int gcol = c * 64 + sub * 8 + tig * 2;
                if (c < 3) {
                    if (r0 < N)
                        *reinterpret_cast<float2*>(&P32[(size_t)r0 * SKIPC + gcol]) =
                            make_float2(acc[sub][t][0], acc[sub][t][1]);
                    if (r1 < N)
                        *reinterpret_cast<float2*>(&P32[(size_t)r1 * SKIPC + gcol]) =
                            make_float2(acc[sub][t][2], acc[sub][t][3]);
                } else {
                    int bcol = gcol - SKIPC;
                    if (r0 < N) {
                        __nv_bfloat162 v = __float22bfloat162_rn(
                            make_float2(acc[sub][t][0], acc[sub][t][1]));
                        *reinterpret_cast<__nv_bfloat162*>(&Pb[(size_t)r0 * RELC + bcol]) = v;
                    }
                    if (r1 < N) {
                        __nv_bfloat162 v = __float22bfloat162_rn(
                            make_float2(acc[sub][t][2], acc[sub][t][3]));
                        *reinterpret_cast<__nv_bfloat162*>(&Pb[(size_t)r1 * RELC + bcol]) = v;
                    }
                }
            }
        }
    }
}

// ---------------- fused FiLM aggregation: one warp per dst node ----------------
__global__ __launch_bounds__(256)
void film_agg(const float* __restrict__ P32, const __nv_bfloat16* __restrict__ Pb,
              const int* __restrict__ off, const int* __restrict__ srcs,
              const float* __restrict__ inv,
              const float* __restrict__ bng, const float* __restrict__ bnb,
              const int* __restrict__ batch,
              float* __restrict__ hout, float* __restrict__ pool, int mode) {
    int node = blockIdx.x * 8 + (threadIdx.x >> 5);
    if (node >= Nn) return;
    int lane = threadIdx.x & 31;

    const float2* row32 = reinterpret_cast<const float2*>(P32 + (size_t)node * SKIPC);
    float2 hw = __ldg(&row32[lane]);
    float2 bs = __ldg(&row32[32 + lane]);
    float2 gs = __ldg(&row32[64 + lane]);
    float ax = fmaxf(gs.x * hw.x + bs.x, 0.f);
    float ay = fmaxf(gs.y * hw.y + bs.y, 0.f);

    const __nv_bfloat162* rowb =
        reinterpret_cast<const __nv_bfloat162*>(Pb + (size_t)node * RELC);

    #pragma unroll
    for (int r = 0; r < Rr; r++) {
        int key = node * Rr + r;
        int beg = __ldg(&off[key]);
        int end = __ldg(&off[key + 1]);
        if (beg == end) continue;
        float ic = __ldg(&inv[key]);
        float2 br = __bfloat1622float2(__ldg(&rowb[r * 96 + 32 + lane]));
        float2 gr = __bfloat1622float2(__ldg(&rowb[r * 96 + 64 + lane]));
        int hoff = r * 96 + lane;
        float sx = 0.f, sy = 0.f;
        int e = beg;
        for (; e + 3 < end; e += 4) {
            int s0 = __ldg(&srcs[e]);
            int s1 = __ldg(&srcs[e + 1]);
            int s2 = __ldg(&srcs[e + 2]);
            int s3 = __ldg(&srcs[e + 3]);
            float2 h0 = __bfloat1622float2(__ldg(
                reinterpret_cast<const __nv_bfloat162*>(Pb + (size_t)s0 * RELC) + hoff));
            float2 h1 = __bfloat1622float2(__ldg(
                reinterpret_cast<const __nv_bfloat162*>(Pb + (size_t)s1 * RELC) + hoff));
            float2 h2 = __bfloat1622float2(__ldg(
                reinterpret_cast<const __nv_bfloat162*>(Pb + (size_t)s2 * RELC) + hoff));
            float2 h3 = __bfloat1622float2(__ldg(
                reinterpret_cast<const __nv_bfloat162*>(Pb + (size_t)s3 * RELC) + hoff));
            sx += fmaxf(gr.x * h0.x + br.x, 0.f) + fmaxf(gr.x * h1.x + br.x, 0.f)
                + fmaxf(gr.x * h2.x + br.x, 0.f) + fmaxf(gr.x * h3.x + br.x, 0.f);
            sy += fmaxf(gr.y * h0.y + br.y, 0.f) + fmaxf(gr.y * h1.y + br.y, 0.f)
                + fmaxf(gr.y * h2.y + br.y, 0.f) + fmaxf(gr.y * h3.y + br.y, 0.f);
        }
        for (; e < end; e++) {
            int s0 = __ldg(&srcs[e]);
            float2 h0 = __bfloat1622float2(__ldg(
                reinterpret_cast<const __nv_bfloat162*>(Pb + (size_t)s0 * RELC) + hoff));
            sx += fmaxf(gr.x * h0.x + br.x, 0.f);
            sy += fmaxf(gr.y * h0.y + br.y, 0.f);
        }
        ax += sx * ic;
        ay += sy * ic;
    }

    int c0 = 2 * lane;
    if (mode == 0) {
        float k = rsqrtf(1.0f + 1e-5f);
        float ox = fmaxf(ax * (__ldg(&bng[c0])     * k) + __ldg(&bnb[c0]),     0.f);
        float oy = fmaxf(ay * (__ldg(&bng[c0 + 1]) * k) + __ldg(&bnb[c0 + 1]), 0.f);
        // output feeds the tf32 GEMM -> pre-round
        *reinterpret_cast<float2*>(&hout[(size_t)node * Hh + c0]) =
            make_float2(rtf32(ox), rtf32(oy));
    } else {
        int g = __ldg(&batch[node]);
        atomicAdd(&pool[g * Hh + c0],     ax);
        atomicAdd(&pool[g * Hh + c0 + 1], ay);
    }
}

// ---------------- head ----------------
__global__ void head1(const float* __restrict__ pool, const float* __restrict__ W,
                      const float* __restrict__ b, float* __restrict__ t) {
    int idx = blockIdx.x * blockDim.x + threadIdx.x;
    if (idx >= Gg * Hh) return;
    int r = idx >> 6, o = idx & 63;
    float s = 0.f;
    #pragma unroll 8
    for (int k = 0; k < Hh; k++) s += pool[r * Hh + k] * W[k * Hh + o];
    t[idx] = fmaxf(s + b[o], 0.f);
}
__global__ void head2(const float* __restrict__ t, const float* __restrict__ W,
                      const float* __restrict__ b, float* __restrict__ out) {
    int idx = blockIdx.x * blockDim.x + threadIdx.x;
    if (idx >= Gg * OUTD) return;
    int r = idx / OUTD, o = idx % OUTD;
    float s = 0.f;
    #pragma unroll 8
    for (int k = 0; k < Hh; k++) s += t[r * Hh + k] * W[k * OUTD + o];
    out[idx] = s + b[o];
}

// ---------------- launch ----------------
extern "C" void kernel_launch(void* const* d_in, const int* in_sizes, int n_in,
                              void* d_out, int out_size) {
    const float* x      = (const float*)d_in[0];
    const int*   ei     = (const int*)  d_in[1];
    const int*   etype  = (const int*)  d_in[2];
    const int*   batch  = (const int*)  d_in[3];
    const float* enc_W  = (const float*)d_in[4];
    const float* enc_b  = (const float*)d_in[5];
    const float* Wskip0 = (const float*)d_in[6];
    const float* Fskip0 = (const float*)d_in[7];
    const float* Wrel0  = (const float*)d_in[8];
    const float* Frel0  = (const float*)d_in[9];
    const float* Wskip1 = (const float*)d_in[10];
    const float* Fskip1 = (const float*)d_in[11];
    const float* Wrel1  = (const float*)d_in[12];
    const float* Frel1  = (const float*)d_in[13];
    const float* bn_g   = (const float*)d_in[14];
    const float* bn_b   = (const float*)d_in[15];
    const float* lin_W  = (const float*)d_in[16];
    const float* lin_b  = (const float*)d_in[17];
    const float* clf_W  = (const float*)d_in[18];
    const float* clf_b  = (const float*)d_in[19];
    float* out = (float*)d_out;

    float *pH, *pP32, *pInv, *pPool, *pT;
    float2* pWp;
    __nv_bfloat16* pPb;
    int *pCnt, *pOff, *pFill, *pBsum, *pSrcs;
    cudaGetSymbolAddress((void**)&pH,    g_h);
    cudaGetSymbolAddress((void**)&pP32,  g_P32);
    cudaGetSymbolAddress((void**)&pPb,   g_Pb);
    cudaGetSymbolAddress((void**)&pCnt,  g_cnt);
    cudaGetSymbolAddress((void**)&pInv,  g_inv);
    cudaGetSymbolAddress((void**)&pOff,  g_off);
    cudaGetSymbolAddress((void**)&pFill, g_fill);
    cudaGetSymbolAddress((void**)&pBsum, g_bsum);
    cudaGetSymbolAddress((void**)&pSrcs, g_srcs);
    cudaGetSymbolAddress((void**)&pWp,   g_Wp);
    cudaGetSymbolAddress((void**)&pPool, g_pool);
    cudaGetSymbolAddress((void**)&pT,    g_t);

    const int NT = 256;
    int gemmBlocks = (Nn + 127) / 128;
    int aggBlocks  = (Nn + 7) / 8;

    // ---- CSR build (layer-invariant) ----
    zero_i<<<(RN + NT - 1) / NT, NT>>>(pCnt, RN);
    count_edges<<<(Ee + 511) / 512, 512>>>(ei, etype, pCnt);
    inv_counts<<<(RN + NT - 1) / NT, NT>>>(pCnt, pInv);
    scan1<<<NBLK, SCAN_B>>>(pCnt, pOff, pBsum);
    scan2<<<1, 512>>>(pBsum, NBLK);
    scan3<<<(RN + NT - 1) / NT, NT>>>(pOff, pBsum);
    zero_i<<<(RN + NT - 1) / NT, NT>>>(pFill, RN);
    scatter_edges<<<(Ee + 511) / 512, 512>>>(ei, etype, pOff, pFill, pSrcs);

    // Encoder: h = tf32_round(x @ enc_W + enc_b)
    {
        dim3 grid(1, (Nn + 63) / 64);
        sgemm<<<grid, 256>>>(x, enc_W, pH, Nn, IND, Hh, enc_b);
    }

    // ---- FiLMConv layer 0 (+ fused BN/ReLU) ----
    repack2<<<(NCHUNK * 2048 + NT - 1) / NT, NT>>>(Wskip0, Fskip0, Wrel0, Frel0, pWp);
    film_gemm_tc<<<gemmBlocks, 128>>>(pH, pWp, pP32, pPb, Nn);
    film_agg<<<aggBlocks, 256>>>(pP32, pPb, pOff, pSrcs, pInv, bn_g, bn_b, batch,
                                 pH, pPool, 0);

    // ---- FiLMConv layer 1 (+ fused global_add_pool) ----
    zero_f<<<(Gg * Hh + NT - 1) / NT, NT>>>(pPool, Gg * Hh);
    repack2<<<(NCHUNK * 2048 + NT - 1) / NT, NT>>>(Wskip1, Fskip1, Wrel1, Frel1, pWp);
    film_gemm_tc<<<gemmBlocks, 128>>>(pH, pWp, pP32, pPb, Nn);
    film_agg<<<aggBlocks, 256>>>(pP32, pPb, pOff, pSrcs, pInv, bn_g, bn_b, batch,
                                 pH, pPool, 1);

    // ---- head ----
    head1<<<(Gg * Hh + NT - 1) / NT, NT>>>(pPool, lin_W, lin_b, pT);
    head2<<<(Gg * OUTD + NT - 1) / NT, NT>>>(pT, clf_W, clf_b, out);
}

// round 12
// speedup vs baseline: 2.1047x; 1.0306x over previous
#include <cuda_runtime.h>
#include <cuda_bf16.h>
#include <math.h>
#include <stdint.h>

// Problem constants
#define Nn   100000
#define Ee   1600000
#define IND  128
#define Hh   64
#define Rr   4
#define Gg   128
#define OUTD 10
#define PCOLS 960
#define SKIPC 192
#define RELC  768
#define RN   (Rr * Nn)
#define SCAN_B 1024
#define NBLK ((RN + SCAN_B - 1) / SCAN_B)
#define NCHUNK 15

// round fp32 -> tf32-representable fp32
__device__ __forceinline__ float rtf32(float x) {
    uint32_t y;
    asm("cvt.rna.tf32.f32 %0, %1;" : "=r"(y) : "f"(x));
    return __uint_as_float(y);
}

// m16n8k8 tf32 mma, D += A*B (fp32 accum in place)
__device__ __forceinline__ void mma_tf32(float* d, const float* a, float b0, float b1) {
    asm("mma.sync.aligned.m16n8k8.row.col.f32.tf32.tf32.f32 "
        "{%0,%1,%2,%3}, {%4,%5,%6,%7}, {%8,%9}, {%0,%1,%2,%3};"
        : "+f"(d[0]), "+f"(d[1]), "+f"(d[2]), "+f"(d[3])
        : "r"(__float_as_uint(a[0])), "r"(__float_as_uint(a[1])),
          "r"(__float_as_uint(a[2])), "r"(__float_as_uint(a[3])),
          "r"(__float_as_uint(b0)), "r"(__float_as_uint(b1)));
}

// ---------------- scratch ----------------
__device__ float4         g_P32[(size_t)Nn * SKIPC / 4];
__device__ __nv_bfloat162 g_Pb [(size_t)Nn * RELC / 2];
__device__ float  g_h  [(size_t)Nn * Hh];
__device__ int    g_cnt [RN];
__device__ float  g_inv [RN];
__device__ int    g_off [RN + 1];
__device__ int    g_bsum[512];
__device__ int    g_srcs[Ee];
__device__ float2 g_Wp [NCHUNK * 2048];   // paired tf32 B fragments (layer GEMM)
__device__ float2 g_Wpe[4096];            // paired tf32 B fragments (encoder)
__device__ float  g_pool[Gg * Hh];
__device__ float  g_t   [Gg * Hh];

// ---------------- small utility kernels ----------------
__global__ void zero_i(int* p, int n) {
    int i = blockIdx.x * blockDim.x + threadIdx.x;
    if (i < n) p[i] = 0;
}
__global__ void zero_f(float* p, int n) {
    int i = blockIdx.x * blockDim.x + threadIdx.x;
    if (i < n) p[i] = 0.f;
}

__global__ void count_edges(const int* __restrict__ ei, const int* __restrict__ et,
                            int* __restrict__ cnt) {
    int e = blockIdx.x * blockDim.x + threadIdx.x;
    if (e < Ee) {
        int d = __ldg(&ei[Ee + e]);
        int r = __ldg(&et[e]);
        atomicAdd(&cnt[d * Rr + r], 1);
    }
}

// ---------------- exclusive scan (inv folded into scan1) ----------------
__global__ void scan1(const int* __restrict__ cnt, int* __restrict__ off,
                      int* __restrict__ bsum, float* __restrict__ inv) {
    __shared__ int sh[SCAN_B];
    int t = threadIdx.x;
    int i = blockIdx.x * SCAN_B + t;
    int v = (i < RN) ? cnt[i] : 0;
    if (i < RN) inv[i] = 1.0f / (float)(v > 0 ? v : 1);
    sh[t] = v;
    __syncthreads();
    for (int d = 1; d < SCAN_B; d <<= 1) {
        int x = (t >= d) ? sh[t - d] : 0;
        __syncthreads();
        sh[t] += x;
        __syncthreads();
    }
    if (i < RN) off[i] = sh[t] - v;
    if (t == SCAN_B - 1) bsum[blockIdx.x] = sh[t];
}
__global__ void scan2(int* __restrict__ bsum, int n) {
    __shared__ int sh[512];
    int t = threadIdx.x;
    int v = (t < n) ? bsum[t] : 0;
    sh[t] = v;
    __syncthreads();
    for (int d = 1; d < 512; d <<= 1) {
        int x = (t >= d) ? sh[t - d] : 0;
        __syncthreads();
        sh[t] += x;
        __syncthreads();
    }
    if (t < n) bsum[t] = sh[t] - v;
}
__global__ void scan3(int* __restrict__ off, const int* __restrict__ bsum) {
    int i = blockIdx.x * blockDim.x + threadIdx.x;
    if (i < RN) off[i] += bsum[i / SCAN_B];
    if (i == 0) off[RN] = Ee;
}

// scatter: reuse cnt as the fill counter (decrement; cnt rebuilt each launch)
__global__ void scatter_edges(const int* __restrict__ ei, const int* __restrict__ et,
                              const int* __restrict__ off, int* __restrict__ cnt,
                              int* __restrict__ srcs) {
    int e = blockIdx.x * blockDim.x + threadIdx.x;
    if (e >= Ee) return;
    int d = __ldg(&ei[Ee + e]);
    int r = __ldg(&et[e]);
    int key = d * Rr + r;
    int old = atomicSub(&cnt[key], 1);
    int pos = off[key] + old - 1;
    srcs[pos] = __ldg(&ei[e]);
}

// weight element W[k][c] of the fused [64 x 960] matrix
__device__ __forceinline__ float wcat_val(int k, int c,
        const float* Wskip, const float* Fskip,
        const float* Wrel,  const float* Frel) {
    if (c < 64)  return Wskip[k * 64 + c];
    if (c < 192) return Fskip[k * 128 + (c - 64)];
    int cc = c - 192;
    int r = cc / 192;
    int o = cc % 192;
    if (o < 64) return Wrel[((size_t)(r * 64 + k)) * 64 + o];
    return Frel[((size_t)(r * 64 + k)) * 128 + (o - 64)];
}

// Repack layer weights into paired tf32 fragment layout:
// Wp[c*2048 + (ks*64+col)*4 + kk] = { W[ks*8+kk][c*64+col], W[ks*8+kk+4][c*64+col] }
__global__ void repack2(const float* __restrict__ Wskip, const float* __restrict__ Fskip,
                        const float* __restrict__ Wrel,  const float* __restrict__ Frel,
                        float2* __restrict__ Wp) {
    int u = blockIdx.x * blockDim.x + threadIdx.x;
    if (u >= NCHUNK * 2048) return;
    int c   = u >> 11;
    int rem = u & 2047;
    int ks  = rem >> 8;
    int rem2 = rem & 255;
    int col = rem2 >> 2;
    int kk  = rem2 & 3;
    int gc = c * 64 + col;
    int k0 = ks * 8 + kk;
    Wp[u] = make_float2(rtf32(wcat_val(k0,     gc, Wskip, Fskip, Wrel, Frel)),
                        rtf32(wcat_val(k0 + 4, gc, Wskip, Fskip, Wrel, Frel)));
}

// Repack encoder weights [128,64] into fragment layout (16 ks steps, 1 chunk)
__global__ void repack_enc(const float* __restrict__ W, float2* __restrict__ Wpe) {
    int u = blockIdx.x * blockDim.x + threadIdx.x;
    if (u >= 4096) return;
    int ks  = u >> 8;
    int rem = u & 255;
    int col = rem >> 2;
    int kk  = rem & 3;
    int k0 = ks * 8 + kk;
    Wpe[u] = make_float2(rtf32(W[k0 * 64 + col]),
                         rtf32(W[(k0 + 4) * 64 + col]));
}

// ---------------- tensor-core encoder: h = tf32(x[N,128] @ W[128,64] + b) -----
__global__ __launch_bounds__(256)
void enc_gemm_tc(const float* __restrict__ X, const float2* __restrict__ Wpe,
                 const float* __restrict__ bias, float* __restrict__ H, int N) {
    __shared__ float2 Bs[4096];   // 32KB
    int tid = threadIdx.x;
    int w = tid >> 5, lane = tid & 31;
    int gid = lane >> 2, tig = lane & 3;
    int n0 = blockIdx.x * 128;

    const float4* src = reinterpret_cast<const float4*>(Wpe);
    float4* dst = reinterpret_cast<float4*>(Bs);
    #pragma unroll
    for (int i = 0; i < 8; i++)
        dst[tid + i * 256] = __ldg(&src[tid + i * 256]);

    float a[16][4];
    int r0 = n0 + w * 16 + gid;
    int r1 = r0 + 8;
    #pragma unroll
    for (int ks = 0; ks < 16; ks++) {
        int c0 = ks * 8 + tig;
        a[ks][0] = (r0 < N) ? rtf32(__ldg(&X[(size_t)r0 * IND + c0]))     : 0.f;
        a[ks][1] = (r1 < N) ? rtf32(__ldg(&X[(size_t)r1 * IND + c0]))     : 0.f;
        a[ks][2] = (r0 < N) ? rtf32(__ldg(&X[(size_t)r0 * IND + c0 + 4])) : 0.f;
        a[ks][3] = (r1 < N) ? rtf32(__ldg(&X[(size_t)r1 * IND + c0 + 4])) : 0.f;
    }
    __syncthreads();

    float acc[8][4];
    #pragma unroll
    for (int s = 0; s < 8; s++)
        #pragma unroll
        for (int j = 0; j < 4; j++) acc[s][j] = 0.f;

    #pragma unroll
    for (int sub = 0; sub < 8; sub++)
        #pragma unroll
        for (int ks = 0; ks < 16; ks++) {
            float2 b = Bs[(ks * 64 + sub * 8 + gid) * 4 + tig];
            mma_tf32(acc[sub], a[ks], b.x, b.y);
        }

    #pragma unroll
    for (int sub = 0; sub < 8; sub++) {
        int col = sub * 8 + tig * 2;
        float b0 = __ldg(&bias[col]), b1 = __ldg(&bias[col + 1]);
        if (r0 < N)
            *reinterpret_cast<float2*>(&H[(size_t)r0 * Hh + col]) =
                make_float2(rtf32(acc[sub][0] + b0), rtf32(acc[sub][1] + b1));
        if (r1 < N)
            *reinterpret_cast<float2*>(&H[(size_t)r1 * Hh + col]) =
                make_float2(rtf32(acc[sub][2] + b0), rtf32(acc[sub][3] + b1));
    }
}

// ---------------- tensor-core layer GEMM: [N,64] @ [64,960] -------------------
__global__ __launch_bounds__(128)
void film_gemm_tc(const float* __restrict__ A, const float2* __restrict__ Wp,
                  float* __restrict__ P32, __nv_bfloat16* __restrict__ Pb, int N) {
    __shared__ float2 Bs[2048];   // 16KB
    int tid = threadIdx.x;
    int w    = tid >> 5;
    int lane = tid & 31;
    int gid  = lane >> 2;
    int tig  = lane & 3;
    int n0 = blockIdx.x * 128;

    float a[2][8][4];
    #pragma unroll
    for (int t = 0; t < 2; t++) {
        int r0 = n0 + w * 32 + t * 16 + gid;
        int r1 = r0 + 8;
        #pragma unroll
        for (int ks = 0; ks < 8; ks++) {
            int c0 = ks * 8 + tig;
            a[t][ks][0] = (r0 < N) ? __ldg(&A[(size_t)r0 * 64 + c0])     : 0.f;
            a[t][ks][1] = (r1 < N) ? __ldg(&A[(size_t)r1 * 64 + c0])     : 0.f;
            a[t][ks][2] = (r0 < N) ? __ldg(&A[(size_t)r0 * 64 + c0 + 4]) : 0.f;
            a[t][ks][3] = (r1 < N) ? __ldg(&A[(size_t)r1 * 64 + c0 + 4]) : 0.f;
        }
    }

    for (int c = 0; c < NCHUNK; c++) {
        __syncthreads();
        const float4* src = reinterpret_cast<const float4*>(Wp + c * 2048);
        float4* dst = reinterpret_cast<float4*>(Bs);
        #pragma unroll
        for (int i = 0; i < 8; i++)
            dst[tid + i * 128] = __ldg(&src[tid + i * 128]);
        __syncthreads();

        float acc[8][2][4];
        #pragma unroll
        for (int s = 0; s < 8; s++)
            #pragma unroll
            for (int t = 0; t < 2; t++)
                #pragma unroll
                for (int j = 0; j < 4; j++) acc[s][t][j] = 0.f;

        #pragma unroll
        for (int sub = 0; sub < 8; sub++) {
            #pragma unroll
            for (int ks = 0; ks < 8; ks++) {
                float2 b = Bs[(ks * 64 + sub * 8 + gid) * 4 + tig];
                mma_tf32(acc[sub][0], a[0][ks], b.x, b.y);
                mma_tf32(acc[sub][1], a[1][ks], b.x, b.y);
            }
        }

        #pragma unroll
        for (int sub = 0; sub < 8; sub++) {
            #pragma unroll
            for (int t = 0; t < 2; t++) {
                int r0 = n0 + w * 32 + t * 16 + gid;
                int r1 = r0 + 8;
                int gcol = c * 64 + sub * 8 + tig * 2;
                if (c < 3) {
                    if (r0 < N)
                        *reinterpret_cast<float2*>(&P32[(size_t)r0 * SKIPC + gcol]) =
                            make_float2(acc[sub][t][0], acc[sub][t][1]);
                    if (r1 < N)
                        *reinterpret_cast<float2*>(&P32[(size_t)r1 * SKIPC + gcol]) =
                            make_float2(acc[sub][t][2], acc[sub][t][3]);
                } else {
                    int bcol = gcol - SKIPC;
                    if (r0 < N) {
                        __nv_bfloat162 v = __float22bfloat162_rn(
                            make_float2(acc[sub][t][0], acc[sub][t][1]));
                        *reinterpret_cast<__nv_bfloat162*>(&Pb[(size_t)r0 * RELC + bcol]) = v;
                    }
                    if (r1 < N) {
                        __nv_bfloat162 v = __float22bfloat162_rn(
                            make_float2(acc[sub][t][2], acc[sub][t][3]));
                        *reinterpret_cast<__nv_bfloat162*>(&Pb[(size_t)r1 * RELC + bcol]) = v;
                    }
                }
            }
        }
    }
}

// ---------------- fused FiLM aggregation: one warp per dst node ----------------
__global__ __launch_bounds__(256)
void film_agg(const float* __restrict__ P32, const __nv_bfloat16* __restrict__ Pb,
              const int* __restrict__ off, const int* __restrict__ srcs,
              const float* __restrict__ inv,
              const float* __restrict__ bng, const float* __restrict__ bnb,
              const int* __restrict__ batch,
              float* __restrict__ hout, float* __restrict__ pool, int mode) {
    int node = blockIdx.x * 8 + (threadIdx.x >> 5);
    if (node >= Nn) return;
    int lane = threadIdx.x & 31;

    const float2* row32 = reinterpret_cast<const float2*>(P32 + (size_t)node * SKIPC);
    float2 hw = __ldg(&row32[lane]);
    float2 bs = __ldg(&row32[32 + lane]);
    float2 gs = __ldg(&row32[64 + lane]);
    float ax = fmaxf(gs.x * hw.x + bs.x, 0.f);
    float ay = fmaxf(gs.y * hw.y + bs.y, 0.f);

    const __nv_bfloat162* rowb =
        reinterpret_cast<const __nv_bfloat162*>(Pb + (size_t)node * RELC);

    #pragma unroll
    for (int r = 0; r < Rr; r++) {
        int key = node * Rr + r;
        int beg = __ldg(&off[key]);
        int end = __ldg(&off[key + 1]);
        if (beg == end) continue;
        float ic = __ldg(&inv[key]);
        float2 br = __bfloat1622float2(__ldg(&rowb[r * 96 + 32 + lane]));
        float2 gr = __bfloat1622float2(__ldg(&rowb[r * 96 + 64 + lane]));
        int hoff = r * 96 + lane;
        float sx = 0.f, sy = 0.f;
        int e = beg;
        for (; e + 3 < end; e += 4) {
            int s0 = __ldg(&srcs[e]);
            int s1 = __ldg(&srcs[e + 1]);
            int s2 = __ldg(&srcs[e + 2]);
            int s3 = __ldg(&srcs[e + 3]);
            float2 h0 = __bfloat1622float2(__ldg(
                reinterpret_cast<const __nv_bfloat162*>(Pb + (size_t)s0 * RELC) + hoff));
            float2 h1 = __bfloat1622float2(__ldg(
                reinterpret_cast<const __nv_bfloat162*>(Pb + (size_t)s1 * RELC) + hoff));
            float2 h2 = __bfloat1622float2(__ldg(
                reinterpret_cast<const __nv_bfloat162*>(Pb + (size_t)s2 * RELC) + hoff));
            float2 h3 = __bfloat1622float2(__ldg(
                reinterpret_cast<const __nv_bfloat162*>(Pb + (size_t)s3 * RELC) + hoff));
            sx += fmaxf(gr.x * h0.x + br.x, 0.f) + fmaxf(gr.x * h1.x + br.x, 0.f)
                + fmaxf(gr.x * h2.x + br.x, 0.f) + fmaxf(gr.x * h3.x + br.x, 0.f);
            sy += fmaxf(gr.y * h0.y + br.y, 0.f) + fmaxf(gr.y * h1.y + br.y, 0.f)
                + fmaxf(gr.y * h2.y + br.y, 0.f) + fmaxf(gr.y * h3.y + br.y, 0.f);
        }
        for (; e < end; e++) {
            int s0 = __ldg(&srcs[e]);
            float2 h0 = __bfloat1622float2(__ldg(
                reinterpret_cast<const __nv_bfloat162*>(Pb + (size_t)s0 * RELC) + hoff));
            sx += fmaxf(gr.x * h0.x + br.x, 0.f);
            sy += fmaxf(gr.y * h0.y + br.y, 0.f);
        }
        ax += sx * ic;
        ay += sy * ic;
    }

    int c0 = 2 * lane;
    if (mode == 0) {
        float k = rsqrtf(1.0f + 1e-5f);
        float ox = fmaxf(ax * (__ldg(&bng[c0])     * k) + __ldg(&bnb[c0]),     0.f);
        float oy = fmaxf(ay * (__ldg(&bng[c0 + 1]) * k) + __ldg(&bnb[c0 + 1]), 0.f);
        *reinterpret_cast<float2*>(&hout[(size_t)node * Hh + c0]) =
            make_float2(rtf32(ox), rtf32(oy));
    } else {
        int g = __ldg(&batch[node]);
        atomicAdd(&pool[g * Hh + c0],     ax);
        atomicAdd(&pool[g * Hh + c0 + 1], ay);
    }
}

// ---------------- head ----------------
__global__ void head1(const float* __restrict__ pool, const float* __restrict__ W,
                      const float* __restrict__ b, float* __restrict__ t) {
    int idx = blockIdx.x * blockDim.x + threadIdx.x;
    if (idx >= Gg * Hh) return;
    int r = idx >> 6, o = idx & 63;
    float s = 0.f;
    #pragma unroll 8
    for (int k = 0; k < Hh; k++) s += pool[r * Hh + k] * W[k * Hh + o];
    t[idx] = fmaxf(s + b[o], 0.f);
}
__global__ void head2(const float* __restrict__ t, const float* __restrict__ W,
                      const float* __restrict__ b, float* __restrict__ out) {
    int idx = blockIdx.x * blockDim.x + threadIdx.x;
    if (idx >= Gg * OUTD) return;
    int r = idx / OUTD, o = idx % OUTD;
    float s = 0.f;
    #pragma unroll 8
    for (int k = 0; k < Hh; k++) s += t[r * Hh + k] * W[k * OUTD + o];
    out[idx] = s + b[o];
}

// ---------------- launch ----------------
extern "C" void kernel_launch(void* const* d_in, const int* in_sizes, int n_in,
                              void* d_out, int out_size) {
    const float* x      = (const float*)d_in[0];
    const int*   ei     = (const int*)  d_in[1];
    const int*   etype  = (const int*)  d_in[2];
    const int*   batch  = (const int*)  d_in[3];
    const float* enc_W  = (const float*)d_in[4];
    const float* enc_b  = (const float*)d_in[5];
    const float* Wskip0 = (const float*)d_in[6];
    const float* Fskip0 = (const float*)d_in[7];
    const float* Wrel0  = (const float*)d_in[8];
    const float* Frel0  = (const float*)d_in[9];
    const float* Wskip1 = (const float*)d_in[10];
    const float* Fskip1 = (const float*)d_in[11];
    const float* Wrel1  = (const float*)d_in[12];
    const float* Frel1  = (const float*)d_in[13];
    const float* bn_g   = (const float*)d_in[14];
    const float* bn_b   = (const float*)d_in[15];
    const float* lin_W  = (const float*)d_in[16];
    const float* lin_b  = (const float*)d_in[17];
    const float* clf_W  = (const float*)d_in[18];
    const float* clf_b  = (const float*)d_in[19];
    float* out = (float*)d_out;

    float *pH, *pP32, *pInv, *pPool, *pT;
    float2 *pWp, *pWpe;
    __nv_bfloat16* pPb;
    int *pCnt, *pOff, *pBsum, *pSrcs;
    cudaGetSymbolAddress((void**)&pH,    g_h);
    cudaGetSymbolAddress((void**)&pP32,  g_P32);
    cudaGetSymbolAddress((void**)&pPb,   g_Pb);
    cudaGetSymbolAddress((void**)&pCnt,  g_cnt);
    cudaGetSymbolAddress((void**)&pInv,  g_inv);
    cudaGetSymbolAddress((void**)&pOff,  g_off);
    cudaGetSymbolAddress((void**)&pBsum, g_bsum);
    cudaGetSymbolAddress((void**)&pSrcs, g_srcs);
    cudaGetSymbolAddress((void**)&pWp,   g_Wp);
    cudaGetSymbolAddress((void**)&pWpe,  g_Wpe);
    cudaGetSymbolAddress((void**)&pPool, g_pool);
    cudaGetSymbolAddress((void**)&pT,    g_t);

    const int NT = 256;
    int gemmBlocks = (Nn + 127) / 128;
    int aggBlocks  = (Nn + 7) / 8;

    // Launch order arranged so ncu (-s 5 -c 1) captures film_gemm_tc (launch #6).
    // 1-2: edge counting (CSR inputs; scan/scatter deferred until after GEMM)
    zero_i<<<(RN + NT - 1) / NT, NT>>>(pCnt, RN);                                   // 1
    count_edges<<<(Ee + 511) / 512, 512>>>(ei, etype, pCnt);                        // 2
    // 3-4: encoder (tensor core)
    repack_enc<<<(4096 + NT - 1) / NT, NT>>>(enc_W, pWpe);                          // 3
    enc_gemm_tc<<<gemmBlocks, 256>>>(x, pWpe, enc_b, pH, Nn);                       // 4
    // 5-6: layer 0 GEMM
    repack2<<<(NCHUNK * 2048 + NT - 1) / NT, NT>>>(Wskip0, Fskip0, Wrel0, Frel0, pWp); // 5
    film_gemm_tc<<<gemmBlocks, 128>>>(pH, pWp, pP32, pPb, Nn);                      // 6 <- profiled
    // 7-10: CSR build (needed only by film_agg)
    scan1<<<NBLK, SCAN_B>>>(pCnt, pOff, pBsum, pInv);                               // 7
    scan2<<<1, 512>>>(pBsum, NBLK);                                                 // 8
    scan3<<<(RN + NT - 1) / NT, NT>>>(pOff, pBsum);                                 // 9
    scatter_edges<<<(Ee + 511) / 512, 512>>>(ei, etype, pOff, pCnt, pSrcs);         // 10
    // 11: layer 0 aggregation (+BN/ReLU)
    film_agg<<<aggBlocks, 256>>>(pP32, pPb, pOff, pSrcs, pInv, bn_g, bn_b, batch,
                                 pH, pPool, 0);                                     // 11
    // 12-15: layer 1
    zero_f<<<(Gg * Hh + NT - 1) / NT, NT>>>(pPool, Gg * Hh);                        // 12
    repack2<<<(NCHUNK * 2048 + NT - 1) / NT, NT>>>(Wskip1, Fskip1, Wrel1, Frel1, pWp); // 13
    film_gemm_tc<<<gemmBlocks, 128>>>(pH, pWp, pP32, pPb, Nn);                      // 14
    film_agg<<<aggBlocks, 256>>>(pP32, pPb, pOff, pSrcs, pInv, bn_g, bn_b, batch,
                                 pH, pPool, 1);                                     // 15
    // 16-17: head
    head1<<<(Gg * Hh + NT - 1) / NT, NT>>>(pPool, lin_W, lin_b, pT);                // 16
    head2<<<(Gg * OUTD + NT - 1) / NT, NT>>>(pT, clf_W, clf_b, out);                // 17
}

// round 14
// speedup vs baseline: 2.1735x; 1.0327x over previous
#include <cuda_runtime.h>
#include <cuda_bf16.h>
#include <math.h>
#include <stdint.h>

// Problem constants
#define Nn   100000
#define Ee   1600000
#define IND  128
#define Hh   64
#define Rr   4
#define Gg   128
#define OUTD 10
#define PCOLS 960
#define SKIPC 192
#define RELC  768
#define RN   (Rr * Nn)
#define SCAN_B 1024
#define NBLK ((RN + SCAN_B - 1) / SCAN_B)
#define NCHUNK 15

// round fp32 -> tf32-representable fp32
__device__ __forceinline__ float rtf32(float x) {
    uint32_t y;
    asm("cvt.rna.tf32.f32 %0, %1;" : "=r"(y) : "f"(x));
    return __uint_as_float(y);
}

// m16n8k8 tf32 mma, D += A*B (fp32 accum in place)
__device__ __forceinline__ void mma_tf32(float* d, const float* a, float b0, float b1) {
    asm("mma.sync.aligned.m16n8k8.row.col.f32.tf32.tf32.f32 "
        "{%0,%1,%2,%3}, {%4,%5,%6,%7}, {%8,%9}, {%0,%1,%2,%3};"
        : "+f"(d[0]), "+f"(d[1]), "+f"(d[2]), "+f"(d[3])
        : "r"(__float_as_uint(a[0])), "r"(__float_as_uint(a[1])),
          "r"(__float_as_uint(a[2])), "r"(__float_as_uint(a[3])),
          "r"(__float_as_uint(b0)), "r"(__float_as_uint(b1)));
}

// ---------------- scratch ----------------
__device__ float4         g_P32[(size_t)Nn * SKIPC / 4];
__device__ __nv_bfloat162 g_Pb [(size_t)Nn * RELC / 2];
__device__ float  g_h  [(size_t)Nn * Hh];
__device__ int    g_cnt [RN];
__device__ float  g_inv [RN];
__device__ int    g_off [RN + 1];
__device__ int    g_bsum[512];
__device__ int    g_srcs[Ee];
__device__ float4 g_Wp4[NCHUNK * 1024];   // paired-subtile tf32 B fragments (layer)
__device__ float2 g_Wpe[4096];            // encoder B fragments
__device__ float  g_pool[Gg * Hh];
__device__ float  g_t   [Gg * Hh];

// ---------------- small utility kernels ----------------
__global__ void zero_i(int* p, int n) {
    int i = blockIdx.x * blockDim.x + threadIdx.x;
    if (i < n) p[i] = 0;
}
__global__ void zero_f(float* p, int n) {
    int i = blockIdx.x * blockDim.x + threadIdx.x;
    if (i < n) p[i] = 0.f;
}

__global__ void count_edges(const int* __restrict__ ei, const int* __restrict__ et,
                            int* __restrict__ cnt) {
    int e = blockIdx.x * blockDim.x + threadIdx.x;
    if (e < Ee) {
        int d = __ldg(&ei[Ee + e]);
        int r = __ldg(&et[e]);
        atomicAdd(&cnt[d * Rr + r], 1);
    }
}

// ---------------- exclusive scan (inv folded into scan1) ----------------
__global__ void scan1(const int* __restrict__ cnt, int* __restrict__ off,
                      int* __restrict__ bsum, float* __restrict__ inv) {
    __shared__ int sh[SCAN_B];
    int t = threadIdx.x;
    int i = blockIdx.x * SCAN_B + t;
    int v = (i < RN) ? cnt[i] : 0;
    if (i < RN) inv[i] = 1.0f / (float)(v > 0 ? v : 1);
    sh[t] = v;
    __syncthreads();
    for (int d = 1; d < SCAN_B; d <<= 1) {
        int x = (t >= d) ? sh[t - d] : 0;
        __syncthreads();
        sh[t] += x;
        __syncthreads();
    }
    if (i < RN) off[i] = sh[t] - v;
    if (t == SCAN_B - 1) bsum[blockIdx.x] = sh[t];
}
__global__ void scan2(int* __restrict__ bsum, int n) {
    __shared__ int sh[512];
    int t = threadIdx.x;
    int v = (t < n) ? bsum[t] : 0;
    sh[t] = v;
    __syncthreads();
    for (int d = 1; d < 512; d <<= 1) {
        int x = (t >= d) ? sh[t - d] : 0;
        __syncthreads();
        sh[t] += x;
        __syncthreads();
    }
    if (t < n) bsum[t] = sh[t] - v;
}
__global__ void scan3(int* __restrict__ off, const int* __restrict__ bsum) {
    int i = blockIdx.x * blockDim.x + threadIdx.x;
    if (i < RN) off[i] += bsum[i / SCAN_B];
    if (i == 0) off[RN] = Ee;
}

// scatter: reuse cnt as fill counter (decrement; cnt rebuilt each launch)
__global__ void scatter_edges(const int* __restrict__ ei, const int* __restrict__ et,
                              const int* __restrict__ off, int* __restrict__ cnt,
                              int* __restrict__ srcs) {
    int e = blockIdx.x * blockDim.x + threadIdx.x;
    if (e >= Ee) return;
    int d = __ldg(&ei[Ee + e]);
    int r = __ldg(&et[e]);
    int key = d * Rr + r;
    int old = atomicSub(&cnt[key], 1);
    int pos = off[key] + old - 1;
    srcs[pos] = __ldg(&ei[e]);
}

// weight element W[k][c] of the fused [64 x 960] matrix
__device__ __forceinline__ float wcat_val(int k, int c,
        const float* Wskip, const float* Fskip,
        const float* Wrel,  const float* Frel) {
    if (c < 64)  return Wskip[k * 64 + c];
    if (c < 192) return Fskip[k * 128 + (c - 64)];
    int cc = c - 192;
    int r = cc / 192;
    int o = cc % 192;
    if (o < 64) return Wrel[((size_t)(r * 64 + k)) * 64 + o];
    return Frel[((size_t)(r * 64 + k)) * 128 + (o - 64)];
}

// Repack layer weights into paired-subtile tf32 fragment layout:
// u = (ks*32 + sp*8 + gid)*4 + tig  within chunk c
// Wp4[c*1024+u] = { W[ks*8+tig][c*64+sp*16+gid],   W[ks*8+tig+4][same col],
//                   W[ks*8+tig][c*64+sp*16+8+gid], W[ks*8+tig+4][same col] }
__global__ void repack3(const float* __restrict__ Wskip, const float* __restrict__ Fskip,
                        const float* __restrict__ Wrel,  const float* __restrict__ Frel,
                        float4* __restrict__ Wp4) {
    int u = blockIdx.x * blockDim.x + threadIdx.x;
    if (u >= NCHUNK * 1024) return;
    int c    = u >> 10;
    int rem  = u & 1023;
    int tig  = rem & 3;
    int rem2 = rem >> 2;          // ks*32 + sp*8 + gid
    int gid  = rem2 & 7;
    int sp   = (rem2 >> 3) & 3;
    int ks   = rem2 >> 5;
    int k0 = ks * 8 + tig;
    int col0 = c * 64 + sp * 16 + gid;
    Wp4[u] = make_float4(
        rtf32(wcat_val(k0,     col0,     Wskip, Fskip, Wrel, Frel)),
        rtf32(wcat_val(k0 + 4, col0,     Wskip, Fskip, Wrel, Frel)),
        rtf32(wcat_val(k0,     col0 + 8, Wskip, Fskip, Wrel, Frel)),
        rtf32(wcat_val(k0 + 4, col0 + 8, Wskip, Fskip, Wrel, Frel)));
}

// Repack encoder weights [128,64] into fragment layout (16 ks steps, 1 chunk)
__global__ void repack_enc(const float* __restrict__ W, float2* __restrict__ Wpe) {
    int u = blockIdx.x * blockDim.x + threadIdx.x;
    if (u >= 4096) return;
    int ks  = u >> 8;
    int rem = u & 255;
    int col = rem >> 2;
    int kk  = rem & 3;
    int k0 = ks * 8 + kk;
    Wpe[u] = make_float2(rtf32(W[k0 * 64 + col]),
                         rtf32(W[(k0 + 4) * 64 + col]));
}

// ---------------- tensor-core encoder: h = tf32(x[N,128] @ W[128,64] + b) -----
__global__ __launch_bounds__(256)
void enc_gemm_tc(const float* __restrict__ X, const float2* __restrict__ Wpe,
                 const float* __restrict__ bias, float* __restrict__ H, int N) {
    __shared__ float2 Bs[4096];   // 32KB
    int tid = threadIdx.x;
    int w = tid >> 5, lane = tid & 31;
    int gid = lane >> 2, tig = lane & 3;
    int n0 = blockIdx.x * 128;

    const float4* src = reinterpret_cast<const float4*>(Wpe);
    float4* dst = reinterpret_cast<float4*>(Bs);
    #pragma unroll
    for (int i = 0; i < 8; i++)
        dst[tid + i * 256] = __ldg(&src[tid + i * 256]);

    float a[16][4];
    int r0 = n0 + w * 16 + gid;
    int r1 = r0 + 8;
    #pragma unroll
    for (int ks = 0; ks < 16; ks++) {
        int c0 = ks * 8 + tig;
        a[ks][0] = (r0 < N) ? rtf32(__ldg(&X[(size_t)r0 * IND + c0]))     : 0.f;
        a[ks][1] = (r1 < N) ? rtf32(__ldg(&X[(size_t)r1 * IND + c0]))     : 0.f;
        a[ks][2] = (r0 < N) ? rtf32(__ldg(&X[(size_t)r0 * IND + c0 + 4])) : 0.f;
        a[ks][3] = (r1 < N) ? rtf32(__ldg(&X[(size_t)r1 * IND + c0 + 4])) : 0.f;
    }
    __syncthreads();

    float acc[8][4];
    #pragma unroll
    for (int s = 0; s < 8; s++)
        #pragma unroll
        for (int j = 0; j < 4; j++) acc[s][j] = 0.f;

    #pragma unroll
    for (int sub = 0; sub < 8; sub++)
        #pragma unroll
        for (int ks = 0; ks < 16; ks++) {
            float2 b = Bs[(ks * 64 + sub * 8 + gid) * 4 + tig];
            mma_tf32(acc[sub], a[ks], b.x, b.y);
        }

    #pragma unroll
    for (int sub = 0; sub < 8; sub++) {
        int col = sub * 8 + tig * 2;
        float b0 = __ldg(&bias[col]), b1 = __ldg(&bias[col + 1]);
        if (r0 < N)
            *reinterpret_cast<float2*>(&H[(size_t)r0 * Hh + col]) =
                make_float2(rtf32(acc[sub][0] + b0), rtf32(acc[sub][1] + b1));
        if (r1 < N)
            *reinterpret_cast<float2*>(&H[(size_t)r1 * Hh + col]) =
                make_float2(rtf32(acc[sub][2] + b0), rtf32(acc[sub][3] + b1));
    }
}

// ---------------- tensor-core layer GEMM: [N,64] @ [64,960] -------------------
// v2: LDS.128 paired-subtile fragments, subpair-scoped accumulators,
// register prefetch of next chunk overlapped with mma.
__global__ __launch_bounds__(128)
void film_gemm_tc(const float* __restrict__ A, const float4* __restrict__ Wp4,
                  float* __restrict__ P32, __nv_bfloat16* __restrict__ Pb, int N) {
    __shared__ float4 Bs[1024];   // 16KB
    int tid = threadIdx.x;
    int w    = tid >> 5;
    int lane = tid & 31;
    int gid  = lane >> 2;
    int tig  = lane & 3;
    int n0 = blockIdx.x * 128;

    // A fragments: 2 row tiles x 8 ks x 4 regs (register-resident all chunks)
    float a[2][8][4];
    #pragma unroll
    for (int t = 0; t < 2; t++) {
        int r0 = n0 + w * 32 + t * 16 + gid;
        int r1 = r0 + 8;
        #pragma unroll
        for (int ks = 0; ks < 8; ks++) {
            int c0 = ks * 8 + tig;
            a[t][ks][0] = (r0 < N) ? __ldg(&A[(size_t)r0 * 64 + c0])     : 0.f;
            a[t][ks][1] = (r1 < N) ? __ldg(&A[(size_t)r1 * 64 + c0])     : 0.f;
            a[t][ks][2] = (r0 < N) ? __ldg(&A[(size_t)r0 * 64 + c0 + 4]) : 0.f;
            a[t][ks][3] = (r1 < N) ? __ldg(&A[(size_t)r1 * 64 + c0 + 4]) : 0.f;
        }
    }

    // preload chunk 0
    float4 st[8];
    #pragma unroll
    for (int i = 0; i < 8; i++) st[i] = __ldg(&Wp4[tid + i * 128]);
    #pragma unroll
    for (int i = 0; i < 8; i++) Bs[tid + i * 128] = st[i];
    __syncthreads();

    for (int c = 0; c < NCHUNK; c++) {
        // prefetch next chunk (latency hidden behind mma)
        if (c + 1 < NCHUNK) {
            const float4* src = Wp4 + (c + 1) * 1024;
            #pragma unroll
            for (int i = 0; i < 8; i++) st[i] = __ldg(&src[tid + i * 128]);
        }

        #pragma unroll
        for (int sp = 0; sp < 4; sp++) {
            float acc[2][2][4];
            #pragma unroll
            for (int ss = 0; ss < 2; ss++)
                #pragma unroll
                for (int t = 0; t < 2; t++)
                    #pragma unroll
                    for (int j = 0; j < 4; j++) acc[ss][t][j] = 0.f;

            #pragma unroll
            for (int ks = 0; ks < 8; ks++) {
                float4 b = Bs[(ks * 32 + sp * 8 + gid) * 4 + tig];
                mma_tf32(acc[0][0], a[0][ks], b.x, b.y);
                mma_tf32(acc[0][1], a[1][ks], b.x, b.y);
                mma_tf32(acc[1][0], a[0][ks], b.z, b.w);
                mma_tf32(acc[1][1], a[1][ks], b.z, b.w);
            }

            // epilogue for subtiles 2sp, 2sp+1
            #pragma unroll
            for (int ss = 0; ss < 2; ss++) {
                int sub = sp * 2 + ss;
                #pragma unroll
                for (int t = 0; t < 2; t++) {
                    int r0 = n0 + w * 32 + t * 16 + gid;
                    int r1 = r0 + 8;
                    int gcol = c * 64 + sub * 8 + tig * 2;
                    if (c < 3) {
                        if (r0 < N)
                            *reinterpret_cast<float2*>(&P32[(size_t)r0 * SKIPC + gcol]) =
                                make_float2(acc[ss][t][0], acc[ss][t][1]);
                        if (r1 < N)
                            *reinterpret_cast<float2*>(&P32[(size_t)r1 * SKIPC + gcol]) =
                                make_float2(acc[ss][t][2], acc[ss][t][3]);
                    } else {
                        int bcol = gcol - SKIPC;
                        if (r0 < N) {
                            __nv_bfloat162 v = __float22bfloat162_rn(
                                make_float2(acc[ss][t][0], acc[ss][t][1]));
                            *reinterpret_cast<__nv_bfloat162*>(&Pb[(size_t)r0 * RELC + bcol]) = v;
                        }
                        if (r1 < N) {
                            __nv_bfloat162 v = __float22bfloat162_rn(
                                make_float2(acc[ss][t][2], acc[ss][t][3]));
                            *reinterpret_cast<__nv_bfloat162*>(&Pb[(size_t)r1 * RELC + bcol]) = v;
                        }
                    }
                }
            }
        }

        if (c + 1 < NCHUNK) {
            __syncthreads();   // everyone done reading Bs
            #pragma unroll
            for (int i = 0; i < 8; i++) Bs[tid + i * 128] = st[i];
            __syncthreads();
        }
    }
}

// ---------------- fused FiLM aggregation: one warp per dst node ----------------
__global__ __launch_bounds__(256)
void film_agg(const float* __restrict__ P32, const __nv_bfloat16* __restrict__ Pb,
              const int* __restrict__ off, const int* __restrict__ srcs,
              const float* __restrict__ inv,
              const float* __restrict__ bng, const float* __restrict__ bnb,
              const int* __restrict__ batch,
              float* __restrict__ hout, float* __restrict__ pool, int mode) {
    int node = blockIdx.x * 8 + (threadIdx.x >> 5);
    if (node >= Nn) return;
    int lane = threadIdx.x & 31;

    const float2* row32 = reinterpret_cast<const float2*>(P32 + (size_t)node * SKIPC);
    float2 hw = __ldg(&row32[lane]);
    float2 bs = __ldg(&row32[32 + lane]);
    float2 gs = __ldg(&row32[64 + lane]);
    float ax = fmaxf(gs.x * hw.x + bs.x, 0.f);
    float ay = fmaxf(gs.y * hw.y + bs.y, 0.f);

    const __nv_bfloat162* rowb =
        reinterpret_cast<const __nv_bfloat162*>(Pb + (size_t)node * RELC);

    #pragma unroll
    for (int r = 0; r < Rr; r++) {
        int key = node * Rr + r;
        int beg = __ldg(&off[key]);
        int end = __ldg(&off[key + 1]);
        if (beg == end) continue;
        float ic = __ldg(&inv[key]);
        float2 br = __bfloat1622float2(__ldg(&rowb[r * 96 + 32 + lane]));
        float2 gr = __bfloat1622float2(__ldg(&rowb[r * 96 + 64 + lane]));
        int hoff = r * 96 + lane;
        float sx = 0.f, sy = 0.f;
        int e = beg;
        for (; e + 3 < end; e += 4) {
            int s0 = __ldg(&srcs[e]);
            int s1 = __ldg(&srcs[e + 1]);
            int s2 = __ldg(&srcs[e + 2]);
            int s3 = __ldg(&srcs[e + 3]);
            float2 h0 = __bfloat1622float2(__ldg(
                reinterpret_cast<const __nv_bfloat162*>(Pb + (size_t)s0 * RELC) + hoff));
            float2 h1 = __bfloat1622float2(__ldg(
                reinterpret_cast<const __nv_bfloat162*>(Pb + (size_t)s1 * RELC) + hoff));
            float2 h2 = __bfloat1622float2(__ldg(
                reinterpret_cast<const __nv_bfloat162*>(Pb + (size_t)s2 * RELC) + hoff));
            float2 h3 = __bfloat1622float2(__ldg(
                reinterpret_cast<const __nv_bfloat162*>(Pb + (size_t)s3 * RELC) + hoff));
            sx += fmaxf(gr.x * h0.x + br.x, 0.f) + fmaxf(gr.x * h1.x + br.x, 0.f)
                + fmaxf(gr.x * h2.x + br.x, 0.f) + fmaxf(gr.x * h3.x + br.x, 0.f);
            sy += fmaxf(gr.y * h0.y + br.y, 0.f) + fmaxf(gr.y * h1.y + br.y, 0.f)
                + fmaxf(gr.y * h2.y + br.y, 0.f) + fmaxf(gr.y * h3.y + br.y, 0.f);
        }
        for (; e < end; e++) {
            int s0 = __ldg(&srcs[e]);
            float2 h0 = __bfloat1622float2(__ldg(
                reinterpret_cast<const __nv_bfloat162*>(Pb + (size_t)s0 * RELC) + hoff));
            sx += fmaxf(gr.x * h0.x + br.x, 0.f);
            sy += fmaxf(gr.y * h0.y + br.y, 0.f);
        }
        ax += sx * ic;
        ay += sy * ic;
    }

    int c0 = 2 * lane;
    if (mode == 0) {
        float k = rsqrtf(1.0f + 1e-5f);
        float ox = fmaxf(ax * (__ldg(&bng[c0])     * k) + __ldg(&bnb[c0]),     0.f);
        float oy = fmaxf(ay * (__ldg(&bng[c0 + 1]) * k) + __ldg(&bnb[c0 + 1]), 0.f);
        *reinterpret_cast<float2*>(&hout[(size_t)node * Hh + c0]) =
            make_float2(rtf32(ox), rtf32(oy));
    } else {
        int g = __ldg(&batch[node]);
        atomicAdd(&pool[g * Hh + c0],     ax);
        atomicAdd(&pool[g * Hh + c0 + 1], ay);
    }
}

// ---------------- head ----------------
__global__ void head1(const float* __restrict__ pool, const float* __restrict__ W,
                      const float* __restrict__ b, float* __restrict__ t) {
    int idx = blockIdx.x * blockDim.x + threadIdx.x;
    if (idx >= Gg * Hh) return;
    int r = idx >> 6, o = idx & 63;
    float s = 0.f;
    #pragma unroll 8
    for (int k = 0; k < Hh; k++) s += pool[r * Hh + k] * W[k * Hh + o];
    t[idx] = fmaxf(s + b[o], 0.f);
}
__global__ void head2(const float* __restrict__ t, const float* __restrict__ W,
                      const float* __restrict__ b, float* __restrict__ out) {
    int idx = blockIdx.x * blockDim.x + threadIdx.x;
    if (idx >= Gg * OUTD) return;
    int r = idx / OUTD, o = idx % OUTD;
    float s = 0.f;
    #pragma unroll 8
    for (int k = 0; k < Hh; k++) s += t[r * Hh + k] * W[k * OUTD + o];
    out[idx] = s + b[o];
}

// ---------------- launch ----------------
extern "C" void kernel_launch(void* const* d_in, const int* in_sizes, int n_in,
                              void* d_out, int out_size) {
    const float* x      = (const float*)d_in[0];
    const int*   ei     = (const int*)  d_in[1];
    const int*   etype  = (const int*)  d_in[2];
    const int*   batch  = (const int*)  d_in[3];
    const float* enc_W  = (const float*)d_in[4];
    const float* enc_b  = (const float*)d_in[5];
    const float* Wskip0 = (const float*)d_in[6];
    const float* Fskip0 = (const float*)d_in[7];
    const float* Wrel0  = (const float*)d_in[8];
    const float* Frel0  = (const float*)d_in[9];
    const float* Wskip1 = (const float*)d_in[10];
    const float* Fskip1 = (const float*)d_in[11];
    const float* Wrel1  = (const float*)d_in[12];
    const float* Frel1  = (const float*)d_in[13];
    const float* bn_g   = (const float*)d_in[14];
    const float* bn_b   = (const float*)d_in[15];
    const float* lin_W  = (const float*)d_in[16];
    const float* lin_b  = (const float*)d_in[17];
    const float* clf_W  = (const float*)d_in[18];
    const float* clf_b  = (const float*)d_in[19];
    float* out = (float*)d_out;

    float *pH, *pP32, *pInv, *pPool, *pT;
    float4* pWp4;
    float2* pWpe;
    __nv_bfloat16* pPb;
    int *pCnt, *pOff, *pBsum, *pSrcs;
    cudaGetSymbolAddress((void**)&pH,    g_h);
    cudaGetSymbolAddress((void**)&pP32,  g_P32);
    cudaGetSymbolAddress((void**)&pPb,   g_Pb);
    cudaGetSymbolAddress((void**)&pCnt,  g_cnt);
    cudaGetSymbolAddress((void**)&pInv,  g_inv);
    cudaGetSymbolAddress((void**)&pOff,  g_off);
    cudaGetSymbolAddress((void**)&pBsum, g_bsum);
    cudaGetSymbolAddress((void**)&pSrcs, g_srcs);
    cudaGetSymbolAddress((void**)&pWp4,  g_Wp4);
    cudaGetSymbolAddress((void**)&pWpe,  g_Wpe);
    cudaGetSymbolAddress((void**)&pPool, g_pool);
    cudaGetSymbolAddress((void**)&pT,    g_t);

    const int NT = 256;
    int gemmBlocks = (Nn + 127) / 128;
    int aggBlocks  = (Nn + 7) / 8;

    // 1-2: edge counting
    zero_i<<<(RN + NT - 1) / NT, NT>>>(pCnt, RN);
    count_edges<<<(Ee + 511) / 512, 512>>>(ei, etype, pCnt);
    // 3-4: encoder (tensor core)
    repack_enc<<<(4096 + NT - 1) / NT, NT>>>(enc_W, pWpe);
    enc_gemm_tc<<<gemmBlocks, 256>>>(x, pWpe, enc_b, pH, Nn);
    // 5-6: layer 0 GEMM
    repack3<<<(NCHUNK * 1024 + NT - 1) / NT, NT>>>(Wskip0, Fskip0, Wrel0, Frel0, pWp4);
    film_gemm_tc<<<gemmBlocks, 128>>>(pH, pWp4, pP32, pPb, Nn);
    // 7-10: CSR build (needed only by film_agg)
    scan1<<<NBLK, SCAN_B>>>(pCnt, pOff, pBsum, pInv);
    scan2<<<1, 512>>>(pBsum, NBLK);
    scan3<<<(RN + NT - 1) / NT, NT>>>(pOff, pBsum);
    scatter_edges<<<(Ee + 511) / 512, 512>>>(ei, etype, pOff, pCnt, pSrcs);
    // 11: layer 0 aggregation (+BN/ReLU)
    film_agg<<<aggBlocks, 256>>>(pP32, pPb, pOff, pSrcs, pInv, bn_g, bn_b, batch,
                                 pH, pPool, 0);
    // 12-15: layer 1
    zero_f<<<(Gg * Hh + NT - 1) / NT, NT>>>(pPool, Gg * Hh);
    repack3<<<(NCHUNK * 1024 + NT - 1) / NT, NT>>>(Wskip1, Fskip1, Wrel1, Frel1, pWp4);
    film_gemm_tc<<<gemmBlocks, 128>>>(pH, pWp4, pP32, pPb, Nn);
    film_agg<<<aggBlocks, 256>>>(pP32, pPb, pOff, pSrcs, pInv, bn_g, bn_b, batch,
                                 pH, pPool, 1);
    // 16-17: head
    head1<<<(Gg * Hh + NT - 1) / NT, NT>>>(pPool, lin_W, lin_b, pT);
    head2<<<(Gg * OUTD + NT - 1) / NT, NT>>>(pT, clf_W, clf_b, out);
}